// round 2
// baseline (speedup 1.0000x reference)
#include <cuda_runtime.h>
#include <math.h>
#include <float.h>

// Problem constants
#define BB   4
#define SS   2048
#define DD   1024
#define HH   16
#define DH   64
#define MROWS (BB*SS)      // 8192

// Scratch (allocation-free rule: __device__ globals)
__device__ float g_q[(size_t)BB*HH*SS*DH];   // (b,h,s,dh)
__device__ float g_k[(size_t)BB*HH*SS*DH];
__device__ float g_v[(size_t)BB*HH*SS*DH];
__device__ float g_att[(size_t)BB*SS*DD];    // (b,s,h*DH+dh)

// ---------------------------------------------------------------------------
// valid_lens may physically be int32 (jax x64 disabled) or int64.
// Little-endian: if int64, words 1 and 3 are high words of elements 0,1 == 0.
// If int32, words 1,3 are random lengths in [0,2048): both zero w.p. ~2^-22.
// ---------------------------------------------------------------------------
__device__ __forceinline__ int load_valid_len(const int* p, int b) {
    bool is64 = (p[1] == 0) && (p[3] == 0);
    int v = is64 ? p[2 * b] : p[b];
    if (v < 0) v = 0;
    if (v > SS) v = SS;
    return v;
}

// ---------------------------------------------------------------------------
// SGEMM: C = A(8192x1024, row-major) @ W(1024x1024, row-major)
// storeMode 0: C row-major; 1: head-major C[((b*H+h)*S+s)*DH+dh]
// Tile: BM=128, BN=128, BK=16; 256 threads; 8x8 per-thread tile.
// ---------------------------------------------------------------------------
__global__ __launch_bounds__(256) void sgemm_kernel(
    const float* __restrict__ A, const float* __restrict__ W,
    float* __restrict__ C, int storeHeadMajor)
{
    __shared__ float As[16][128];   // transposed A tile: As[k][m]
    __shared__ float Ws[16][128];   // Ws[k][n]

    const int tid = threadIdx.x;
    const int bm  = blockIdx.y * 128;
    const int bn  = blockIdx.x * 128;
    const int tx  = tid & 15;
    const int ty  = tid >> 4;

    float acc[8][8];
#pragma unroll
    for (int i = 0; i < 8; i++)
#pragma unroll
        for (int j = 0; j < 8; j++) acc[i][j] = 0.f;

    const int K = DD, N = DD;

    for (int k0 = 0; k0 < K; k0 += 16) {
#pragma unroll
        for (int i = 0; i < 2; i++) {
            int f   = tid + i * 256;
            int row = f >> 2;
            int c4  = f & 3;
            float4 v = *(const float4*)(A + (size_t)(bm + row) * K + k0 + c4 * 4);
            As[c4 * 4 + 0][row] = v.x;
            As[c4 * 4 + 1][row] = v.y;
            As[c4 * 4 + 2][row] = v.z;
            As[c4 * 4 + 3][row] = v.w;
        }
#pragma unroll
        for (int i = 0; i < 2; i++) {
            int f   = tid + i * 256;
            int row = f >> 5;
            int c4  = f & 31;
            *(float4*)(&Ws[row][c4 * 4]) =
                *(const float4*)(W + (size_t)(k0 + row) * N + bn + c4 * 4);
        }
        __syncthreads();

#pragma unroll
        for (int kk = 0; kk < 16; kk++) {
            float ra[8], rb[8];
            float4 a0 = *(const float4*)&As[kk][ty * 8];
            float4 a1 = *(const float4*)&As[kk][ty * 8 + 4];
            float4 b0 = *(const float4*)&Ws[kk][tx * 8];
            float4 b1 = *(const float4*)&Ws[kk][tx * 8 + 4];
            ra[0]=a0.x; ra[1]=a0.y; ra[2]=a0.z; ra[3]=a0.w;
            ra[4]=a1.x; ra[5]=a1.y; ra[6]=a1.z; ra[7]=a1.w;
            rb[0]=b0.x; rb[1]=b0.y; rb[2]=b0.z; rb[3]=b0.w;
            rb[4]=b1.x; rb[5]=b1.y; rb[6]=b1.z; rb[7]=b1.w;
#pragma unroll
            for (int i = 0; i < 8; i++)
#pragma unroll
                for (int j = 0; j < 8; j++)
                    acc[i][j] += ra[i] * rb[j];
        }
        __syncthreads();
    }

    if (!storeHeadMajor) {
#pragma unroll
        for (int i = 0; i < 8; i++) {
            int row = bm + ty * 8 + i;
            float* cp = C + (size_t)row * N + bn + tx * 8;
            *(float4*)(cp)     = make_float4(acc[i][0], acc[i][1], acc[i][2], acc[i][3]);
            *(float4*)(cp + 4) = make_float4(acc[i][4], acc[i][5], acc[i][6], acc[i][7]);
        }
    } else {
#pragma unroll
        for (int i = 0; i < 8; i++) {
            int row = bm + ty * 8 + i;
            int b   = row >> 11;
            int s   = row & 2047;
            int col0 = bn + tx * 8;
            int h    = col0 >> 6;
            int dh0  = col0 & 63;
            float* cp = C + (((size_t)(b * HH + h)) * SS + s) * DH + dh0;
            *(float4*)(cp)     = make_float4(acc[i][0], acc[i][1], acc[i][2], acc[i][3]);
            *(float4*)(cp + 4) = make_float4(acc[i][4], acc[i][5], acc[i][6], acc[i][7]);
        }
    }
}

// ---------------------------------------------------------------------------
// Attention: flash-style, one warp per query row, 8 warps/block.
// Grid: (S/8=256, B*H=64). K tile = 32 keys, K transposed in smem (pad 33).
// valid_len==0 -> softmax of all -1e20 == uniform over all S keys.
// ---------------------------------------------------------------------------
__global__ __launch_bounds__(256) void attn_kernel(
    const int* __restrict__ valid_lens_raw, float* __restrict__ out)
{
    __shared__ float q_s[8 * 64];
    __shared__ float ks[64 * 33];
    __shared__ float vs[32 * 64];

    const int tid  = threadIdx.x;
    const int w    = tid >> 5;
    const int lane = tid & 31;
    const int bh   = blockIdx.y;
    const int b    = bh >> 4;
    const int h    = bh & 15;

    const int L = load_valid_len(valid_lens_raw, b);
    const bool uniform = (L == 0);
    const int Leff = uniform ? SS : L;
    const int qi = blockIdx.x * 8 + w;

    const float* qptr = g_q + ((size_t)bh * SS + qi) * DH;
    q_s[w * 64 + lane]      = qptr[lane];
    q_s[w * 64 + lane + 32] = qptr[lane + 32];

    float m = -INFINITY, l = 0.f, o0 = 0.f, o1 = 0.f;
    const int nt = (Leff + 31) >> 5;

    for (int t = 0; t < nt; t++) {
        const int kb = t * 32;
#pragma unroll
        for (int i = 0; i < 2; i++) {
            int f4 = tid + i * 256;
            int j  = f4 >> 4;
            int dq = f4 & 15;
            const size_t base = ((size_t)bh * SS + kb + j) * DH + dq * 4;
            float4 kv = *(const float4*)(g_k + base);
            ks[(dq * 4 + 0) * 33 + j] = kv.x;
            ks[(dq * 4 + 1) * 33 + j] = kv.y;
            ks[(dq * 4 + 2) * 33 + j] = kv.z;
            ks[(dq * 4 + 3) * 33 + j] = kv.w;
            float4 vv = *(const float4*)(g_v + base);
            *(float4*)(&vs[j * 64 + dq * 4]) = vv;
        }
        __syncthreads();

        const int kj = kb + lane;
        const bool valid = kj < Leff;
        float s;
        if (uniform) {
            s = 0.f;
        } else {
            float acc = 0.f;
            const float* qrow = &q_s[w * 64];
#pragma unroll 8
            for (int d = 0; d < 64; d++)
                acc += qrow[d] * ks[d * 33 + lane];
            s = acc * 0.125f;               // 1/sqrt(64)
        }
        float sm = valid ? s : -FLT_MAX;
#pragma unroll
        for (int off = 16; off > 0; off >>= 1)
            sm = fmaxf(sm, __shfl_xor_sync(0xffffffffu, sm, off));
        const float mn = fmaxf(m, sm);
        float p = valid ? __expf(s - mn) : 0.f;
        const float alpha = __expf(m - mn);
        float psum = p;
#pragma unroll
        for (int off = 16; off > 0; off >>= 1)
            psum += __shfl_xor_sync(0xffffffffu, psum, off);
        l = l * alpha + psum;
        o0 *= alpha; o1 *= alpha;
#pragma unroll
        for (int j = 0; j < 32; j++) {
            float pj = __shfl_sync(0xffffffffu, p, j);
            o0 += pj * vs[j * 64 + lane];
            o1 += pj * vs[j * 64 + 32 + lane];
        }
        m = mn;
        __syncthreads();
    }

    const float inv = 1.f / l;
    float* op = out + ((size_t)(b * SS + qi)) * DD + h * DH;
    op[lane]      = o0 * inv;
    op[lane + 32] = o1 * inv;
}

// ---------------------------------------------------------------------------
extern "C" void kernel_launch(void* const* d_in, const int* in_sizes, int n_in,
                              void* d_out, int out_size)
{
    const float* Q  = (const float*)d_in[0];
    const float* Km = (const float*)d_in[1];
    const float* V  = (const float*)d_in[2];
    const int*   vl = (const int*)d_in[3];
    const float* Wq = (const float*)d_in[4];
    const float* Wk = (const float*)d_in[5];
    const float* Wv = (const float*)d_in[6];
    const float* Wo = (const float*)d_in[7];
    float* out = (float*)d_out;

    float *pq, *pk, *pv, *pa;
    cudaGetSymbolAddress((void**)&pq, g_q);
    cudaGetSymbolAddress((void**)&pk, g_k);
    cudaGetSymbolAddress((void**)&pv, g_v);
    cudaGetSymbolAddress((void**)&pa, g_att);

    dim3 gGemm(DD / 128, MROWS / 128);   // (8, 64)
    sgemm_kernel<<<gGemm, 256>>>(Q,  Wq, pq, 1);
    sgemm_kernel<<<gGemm, 256>>>(Km, Wk, pk, 1);
    sgemm_kernel<<<gGemm, 256>>>(V,  Wv, pv, 1);

    dim3 gAttn(SS / 8, BB * HH);         // (256, 64)
    attn_kernel<<<gAttn, 256>>>(vl, pa);

    sgemm_kernel<<<gGemm, 256>>>(pa, Wo, out, 0);
}

// round 3
// speedup vs baseline: 1.4567x; 1.4567x over previous
#include <cuda_runtime.h>
#include <math.h>
#include <float.h>

// Problem constants
#define BB   4
#define SS   2048
#define DD   1024
#define HH   16
#define DH   64
#define MROWS (BB*SS)      // 8192

typedef unsigned long long u64;

// Scratch (allocation-free rule: __device__ globals)
__device__ float g_q[(size_t)BB*HH*SS*DH];   // (b,h,s,dh)
__device__ float g_k[(size_t)BB*HH*SS*DH];
__device__ float g_v[(size_t)BB*HH*SS*DH];
__device__ float g_att[(size_t)BB*SS*DD];    // (b,s,h*DH+dh)

// ---------------------------------------------------------------------------
// valid_lens may physically be int32 (jax x64 disabled) or int64.
// ---------------------------------------------------------------------------
__device__ __forceinline__ int load_valid_len(const int* p, int b) {
    bool is64 = (p[1] == 0) && (p[3] == 0);
    int v = is64 ? p[2 * b] : p[b];
    if (v < 0) v = 0;
    if (v > SS) v = SS;
    return v;
}

// packed fp32 pair helpers (sm_100+ f32x2 pipe)
__device__ __forceinline__ void fma2(u64& d, u64 a, u64 b) {
    asm("fma.rn.f32x2 %0, %1, %2, %0;" : "+l"(d) : "l"(a), "l"(b));
}
__device__ __forceinline__ u64 dup2(float x) {
    u64 r; asm("mov.b64 %0, {%1, %1};" : "=l"(r) : "f"(x)); return r;
}

// ---------------------------------------------------------------------------
// SGEMM: C = A(8192x1024) @ W(1024x1024), row-major inputs.
// storeHeadMajor 0: C row-major; 1: C[((b*H+h)*S+s)*DH+dh]
// BM=BN=128, BK=16, 256 thr, 8x8/thread, f32x2 packed FMA, double-buffered.
// ---------------------------------------------------------------------------
__global__ __launch_bounds__(256) void sgemm_kernel(
    const float* __restrict__ A, const float* __restrict__ W,
    float* __restrict__ C, int storeHeadMajor)
{
    __shared__ float As[2][16][128];   // As[buf][k][m]
    __shared__ float Ws[2][16][128];   // Ws[buf][k][n]

    const int tid = threadIdx.x;
    const int bm  = blockIdx.y * 128;
    const int bn  = blockIdx.x * 128;
    const int tx  = tid & 15;
    const int ty  = tid >> 4;
    const int K = DD, N = DD;

    u64 acc2[8][4];
#pragma unroll
    for (int i = 0; i < 8; i++)
#pragma unroll
        for (int j = 0; j < 4; j++) acc2[i][j] = 0ull;

    float4 ra4[2], rw4[2];
    // preload tile k0=0 into regs
#pragma unroll
    for (int i = 0; i < 2; i++) {
        int f4 = tid + i * 256;
        ra4[i] = *(const float4*)(A + (size_t)(bm + (f4 >> 2)) * K + (f4 & 3) * 4);
        rw4[i] = *(const float4*)(W + (size_t)(f4 >> 5) * N + bn + (f4 & 31) * 4);
    }
    // store to buffer 0
#pragma unroll
    for (int i = 0; i < 2; i++) {
        int f4 = tid + i * 256;
        int rowA = f4 >> 2, c4A = f4 & 3;
        As[0][c4A * 4 + 0][rowA] = ra4[i].x;
        As[0][c4A * 4 + 1][rowA] = ra4[i].y;
        As[0][c4A * 4 + 2][rowA] = ra4[i].z;
        As[0][c4A * 4 + 3][rowA] = ra4[i].w;
        *(float4*)(&Ws[0][f4 >> 5][(f4 & 31) * 4]) = rw4[i];
    }
    __syncthreads();

    int buf = 0;
    for (int k0 = 16; k0 <= K; k0 += 16) {
        if (k0 < K) {
            // issue next-tile loads (latency hidden under compute)
#pragma unroll
            for (int i = 0; i < 2; i++) {
                int f4 = tid + i * 256;
                ra4[i] = *(const float4*)(A + (size_t)(bm + (f4 >> 2)) * K + k0 + (f4 & 3) * 4);
                rw4[i] = *(const float4*)(W + (size_t)(k0 + (f4 >> 5)) * N + bn + (f4 & 31) * 4);
            }
        }
#pragma unroll
        for (int kk = 0; kk < 16; kk++) {
            float4 a0 = *(const float4*)&As[buf][kk][ty * 8];
            float4 a1 = *(const float4*)&As[buf][kk][ty * 8 + 4];
            ulonglong2 b01 = *(const ulonglong2*)&Ws[buf][kk][tx * 8];
            ulonglong2 b23 = *(const ulonglong2*)&Ws[buf][kk][tx * 8 + 4];
            float ra[8] = {a0.x, a0.y, a0.z, a0.w, a1.x, a1.y, a1.z, a1.w};
#pragma unroll
            for (int i = 0; i < 8; i++) {
                u64 aa = dup2(ra[i]);
                fma2(acc2[i][0], aa, b01.x);
                fma2(acc2[i][1], aa, b01.y);
                fma2(acc2[i][2], aa, b23.x);
                fma2(acc2[i][3], aa, b23.y);
            }
        }
        if (k0 < K) {
            __syncthreads();
#pragma unroll
            for (int i = 0; i < 2; i++) {
                int f4 = tid + i * 256;
                int rowA = f4 >> 2, c4A = f4 & 3;
                int nb = buf ^ 1;
                As[nb][c4A * 4 + 0][rowA] = ra4[i].x;
                As[nb][c4A * 4 + 1][rowA] = ra4[i].y;
                As[nb][c4A * 4 + 2][rowA] = ra4[i].z;
                As[nb][c4A * 4 + 3][rowA] = ra4[i].w;
                *(float4*)(&Ws[nb][f4 >> 5][(f4 & 31) * 4]) = rw4[i];
            }
            __syncthreads();
            buf ^= 1;
        }
    }

    // epilogue
    if (!storeHeadMajor) {
#pragma unroll
        for (int i = 0; i < 8; i++) {
            int row = bm + ty * 8 + i;
            float* cp = C + (size_t)row * N + bn + tx * 8;
            *(ulonglong2*)(cp)     = make_ulonglong2(acc2[i][0], acc2[i][1]);
            *(ulonglong2*)(cp + 4) = make_ulonglong2(acc2[i][2], acc2[i][3]);
        }
    } else {
#pragma unroll
        for (int i = 0; i < 8; i++) {
            int row = bm + ty * 8 + i;
            int b   = row >> 11;
            int s   = row & 2047;
            int col0 = bn + tx * 8;
            int h    = col0 >> 6;
            int dh0  = col0 & 63;
            float* cp = C + (((size_t)(b * HH + h)) * SS + s) * DH + dh0;
            *(ulonglong2*)(cp)     = make_ulonglong2(acc2[i][0], acc2[i][1]);
            *(ulonglong2*)(cp + 4) = make_ulonglong2(acc2[i][2], acc2[i][3]);
        }
    }
}

// ---------------------------------------------------------------------------
// Attention v2: 4 queries per warp, 8 warps/block = 32 queries/block.
// Grid: (S/32=64, B*H=64). Tile = 32 keys.
// K in smem as float4 [dq][key] (pad stride 33) -> conflict-free LDS.128.
// p broadcast via float4 per warp in smem (no shuffle storm in PV).
// valid_len==0 -> softmax of all -1e20 == uniform over all S keys.
// ---------------------------------------------------------------------------
__global__ __launch_bounds__(256) void attn_kernel(
    const int* __restrict__ valid_lens_raw, float* __restrict__ out)
{
    __shared__ float4 q4[32 * 16];     // [q_local][dq]          8KB
    __shared__ float4 ks4[16 * 33];    // [dq][key] padded       8.25KB
    __shared__ float  vs[32 * 64];     // [key][dim]             8KB
    __shared__ float4 ps4[8 * 32];     // [warp][key] = p x4q    4KB

    const int tid  = threadIdx.x;
    const int w    = tid >> 5;
    const int lane = tid & 31;
    const int bh   = blockIdx.y;
    const int b    = bh >> 4;
    const int h    = bh & 15;

    const int L = load_valid_len(valid_lens_raw, b);
    const bool uniform = (L == 0);
    const int Leff = uniform ? SS : L;
    const int q0 = blockIdx.x * 32;

    // load 32 queries x 64 dims
#pragma unroll
    for (int i = 0; i < 2; i++) {
        int f4 = tid + i * 256;            // f4 = q_local*16 + dq
        q4[f4] = *(const float4*)(g_q + ((size_t)bh * SS + q0 + (f4 >> 4)) * DH + (f4 & 15) * 4);
    }

    float m[4], l[4];
    float2 o[4];
#pragma unroll
    for (int qq = 0; qq < 4; qq++) {
        m[qq] = -INFINITY; l[qq] = 0.f; o[qq] = make_float2(0.f, 0.f);
    }

    const int nt = (Leff + 31) >> 5;
    for (int t = 0; t < nt; t++) {
        const int kb = t * 32;
        __syncthreads();   // protect ks4/vs from previous iteration readers
#pragma unroll
        for (int i = 0; i < 2; i++) {
            int f4 = tid + i * 256;
            int j  = f4 >> 4;
            int dq = f4 & 15;
            const size_t base = ((size_t)bh * SS + kb + j) * DH + dq * 4;
            ks4[dq * 33 + j] = *(const float4*)(g_k + base);
            *(float4*)(&vs[j * 64 + dq * 4]) = *(const float4*)(g_v + base);
        }
        __syncthreads();

        // scores: lane = key
        float s[4] = {0.f, 0.f, 0.f, 0.f};
        if (!uniform) {
#pragma unroll
            for (int dq = 0; dq < 16; dq++) {
                float4 kv = ks4[dq * 33 + lane];
#pragma unroll
                for (int qq = 0; qq < 4; qq++) {
                    float4 qv = q4[(w * 4 + qq) * 16 + dq];
                    s[qq] += qv.x * kv.x + qv.y * kv.y + qv.z * kv.z + qv.w * kv.w;
                }
            }
#pragma unroll
            for (int qq = 0; qq < 4; qq++) s[qq] *= 0.125f;   // 1/sqrt(64)
        }

        const bool valid = (kb + lane) < Leff;
        float p[4];
#pragma unroll
        for (int qq = 0; qq < 4; qq++) {
            float sv = valid ? s[qq] : -FLT_MAX;
#pragma unroll
            for (int off = 16; off > 0; off >>= 1)
                sv = fmaxf(sv, __shfl_xor_sync(0xffffffffu, sv, off));
            const float mn = fmaxf(m[qq], sv);
            p[qq] = valid ? __expf(s[qq] - mn) : 0.f;
            const float alpha = __expf(m[qq] - mn);
            float psum = p[qq];
#pragma unroll
            for (int off = 16; off > 0; off >>= 1)
                psum += __shfl_xor_sync(0xffffffffu, psum, off);
            l[qq] = l[qq] * alpha + psum;
            o[qq].x *= alpha; o[qq].y *= alpha;
            m[qq] = mn;
        }
        ps4[w * 32 + lane] = make_float4(p[0], p[1], p[2], p[3]);
        __syncwarp();

        // PV: lane owns dims (2*lane, 2*lane+1)
#pragma unroll 8
        for (int j = 0; j < 32; j++) {
            float4 pj = ps4[w * 32 + j];
            float2 vv = *(const float2*)&vs[j * 64 + lane * 2];
            o[0].x += pj.x * vv.x; o[0].y += pj.x * vv.y;
            o[1].x += pj.y * vv.x; o[1].y += pj.y * vv.y;
            o[2].x += pj.z * vv.x; o[2].y += pj.z * vv.y;
            o[3].x += pj.w * vv.x; o[3].y += pj.w * vv.y;
        }
    }

#pragma unroll
    for (int qq = 0; qq < 4; qq++) {
        const float inv = 1.f / l[qq];
        const int qi = q0 + w * 4 + qq;
        float* op = out + ((size_t)(b * SS + qi)) * DD + h * DH + lane * 2;
        op[0] = o[qq].x * inv;
        op[1] = o[qq].y * inv;
    }
}

// ---------------------------------------------------------------------------
extern "C" void kernel_launch(void* const* d_in, const int* in_sizes, int n_in,
                              void* d_out, int out_size)
{
    const float* Q  = (const float*)d_in[0];
    const float* Km = (const float*)d_in[1];
    const float* V  = (const float*)d_in[2];
    const int*   vl = (const int*)d_in[3];
    const float* Wq = (const float*)d_in[4];
    const float* Wk = (const float*)d_in[5];
    const float* Wv = (const float*)d_in[6];
    const float* Wo = (const float*)d_in[7];
    float* out = (float*)d_out;

    float *pq, *pk, *pv, *pa;
    cudaGetSymbolAddress((void**)&pq, g_q);
    cudaGetSymbolAddress((void**)&pk, g_k);
    cudaGetSymbolAddress((void**)&pv, g_v);
    cudaGetSymbolAddress((void**)&pa, g_att);

    dim3 gGemm(DD / 128, MROWS / 128);   // (8, 64)
    sgemm_kernel<<<gGemm, 256>>>(Q,  Wq, pq, 1);
    sgemm_kernel<<<gGemm, 256>>>(Km, Wk, pk, 1);
    sgemm_kernel<<<gGemm, 256>>>(V,  Wv, pv, 1);

    dim3 gAttn(SS / 32, BB * HH);        // (64, 64)
    attn_kernel<<<gAttn, 256>>>(vl, pa);

    sgemm_kernel<<<gGemm, 256>>>(pa, Wo, out, 0);
}

// round 5
// speedup vs baseline: 2.3421x; 1.6078x over previous
#include <cuda_runtime.h>
#include <cuda_bf16.h>
#include <math.h>
#include <float.h>
#include <stdint.h>

// Problem constants
#define BB   4
#define SS   2048
#define DD   1024
#define HH   16
#define DH   64
#define MROWS (BB*SS)      // 8192

// ---------------------------------------------------------------------------
// Scratch (allocation-free rule: __device__ globals)
// ---------------------------------------------------------------------------
__device__ float g_q[(size_t)BB*HH*SS*DH];   // (b,h,s,dh)
__device__ float g_k[(size_t)BB*HH*SS*DH];
__device__ float g_v[(size_t)BB*HH*SS*DH];
__device__ float g_att[(size_t)BB*SS*DD];    // (b,s,h*DH+dh)

#define NEL ((size_t)MROWS*DD)               // 8M elements
__device__ __align__(16) __nv_bfloat16 g_qh[NEL], g_ql[NEL];
__device__ __align__(16) __nv_bfloat16 g_kh[NEL], g_kl[NEL];
__device__ __align__(16) __nv_bfloat16 g_vh[NEL], g_vl[NEL];
__device__ __align__(16) __nv_bfloat16 g_ch[NEL], g_cl[NEL];
__device__ __align__(16) __nv_bfloat16 g_wth[4][DD*DD], g_wtl[4][DD*DD];

// ---------------------------------------------------------------------------
// helpers
// ---------------------------------------------------------------------------
__device__ __forceinline__ uint32_t smem_u32(const void* p) {
    uint32_t a;
    asm("{ .reg .u64 t; cvta.to.shared.u64 t, %1; cvt.u32.u64 %0, t; }" : "=r"(a) : "l"(p));
    return a;
}
__device__ __forceinline__ void cp16(uint32_t dst, const void* src) {
    asm volatile("cp.async.cg.shared.global [%0], [%1], 16;" :: "r"(dst), "l"(src));
}
#define CP_COMMIT() asm volatile("cp.async.commit_group;" ::: "memory")
#define CP_WAIT1()  asm volatile("cp.async.wait_group 1;" ::: "memory")
#define CP_WAIT0()  asm volatile("cp.async.wait_group 0;" ::: "memory")

__device__ __forceinline__ void ldsm4(uint32_t& r0, uint32_t& r1, uint32_t& r2, uint32_t& r3,
                                      uint32_t addr) {
    asm volatile("ldmatrix.sync.aligned.m8n8.x4.shared.b16 {%0,%1,%2,%3}, [%4];"
                 : "=r"(r0), "=r"(r1), "=r"(r2), "=r"(r3) : "r"(addr));
}
__device__ __forceinline__ void mma_bf16(float* c, const uint32_t* a, const uint32_t* b) {
    asm volatile(
        "mma.sync.aligned.m16n8k16.row.col.f32.bf16.bf16.f32 "
        "{%0,%1,%2,%3}, {%4,%5,%6,%7}, {%8,%9}, {%0,%1,%2,%3};"
        : "+f"(c[0]), "+f"(c[1]), "+f"(c[2]), "+f"(c[3])
        : "r"(a[0]), "r"(a[1]), "r"(a[2]), "r"(a[3]), "r"(b[0]), "r"(b[1]));
}

// ---------------------------------------------------------------------------
// valid_lens may physically be int32 (jax x64 disabled) or int64.
// ---------------------------------------------------------------------------
__device__ __forceinline__ int load_valid_len(const int* p, int b) {
    bool is64 = (p[1] == 0) && (p[3] == 0);
    int v = is64 ? p[2 * b] : p[b];
    if (v < 0) v = 0;
    if (v > SS) v = SS;
    return v;
}

// ---------------------------------------------------------------------------
// Elementwise fp32 -> (hi, lo) bf16 split. 4 elems/thread.
// ---------------------------------------------------------------------------
__global__ __launch_bounds__(256) void split_kernel(
    const float4* __restrict__ in, ushort4* __restrict__ hi, ushort4* __restrict__ lo)
{
    int i = blockIdx.x * 256 + threadIdx.x;
    float4 v = in[i];
    float f[4] = {v.x, v.y, v.z, v.w};
    unsigned short h[4], l[4];
#pragma unroll
    for (int j = 0; j < 4; j++) {
        __nv_bfloat16 hb = __float2bfloat16_rn(f[j]);
        __nv_bfloat16 lb = __float2bfloat16_rn(f[j] - __bfloat162float(hb));
        h[j] = __bfloat16_as_ushort(hb);
        l[j] = __bfloat16_as_ushort(lb);
    }
    hi[i] = make_ushort4(h[0], h[1], h[2], h[3]);
    lo[i] = make_ushort4(l[0], l[1], l[2], l[3]);
}

// ---------------------------------------------------------------------------
// W[k,n] (1024x1024 row-major) -> wt_hi/wt_lo[n,k] bf16 (transpose + split)
// ---------------------------------------------------------------------------
__global__ __launch_bounds__(256) void wsplit_kernel(
    const float* __restrict__ W, __nv_bfloat16* __restrict__ th, __nv_bfloat16* __restrict__ tl)
{
    __shared__ float tile[32][33];
    const int tx = threadIdx.x, ty = threadIdx.y;      // (32, 8)
    const int bk = blockIdx.x * 32, bn = blockIdx.y * 32;
#pragma unroll
    for (int i = 0; i < 4; i++)
        tile[ty + 8 * i][tx] = W[(size_t)(bk + ty + 8 * i) * DD + bn + tx];
    __syncthreads();
#pragma unroll
    for (int i = 0; i < 4; i++) {
        float f = tile[tx][ty + 8 * i];                // [k=bk+tx][n=bn+ty+8i]
        __nv_bfloat16 hb = __float2bfloat16_rn(f);
        __nv_bfloat16 lb = __float2bfloat16_rn(f - __bfloat162float(hb));
        size_t o = (size_t)(bn + ty + 8 * i) * DD + bk + tx;
        th[o] = hb; tl[o] = lb;
    }
}

// ---------------------------------------------------------------------------
// Tensor-core GEMM via mma.sync bf16 (base-target PTX; runs on sm_103):
//   C(8192x1024) = A @ W,  A ~ a_hi + a_lo (row-major [m,k] bf16),
//   W^T ~ bt_hi + bt_lo ([n,k] bf16 K-major).
// 3-term split: Ah*Bh + Ah*Bl + Al*Bh.
// CTA tile 128x128, 8 warps (2m x 4n), warp tile 64x32.
// K-chunk 64, 2-stage cp.async pipeline.
// smem per stage: 4 tiles [128][72] bf16 (pad 8 -> conflict-free LDSM).
// ---------------------------------------------------------------------------
#define PADK    72
#define TILE_B  (128*PADK*2)        // 18432 bytes
#define OFF_AH  0
#define OFF_AL  (1*TILE_B)
#define OFF_BH  (2*TILE_B)
#define OFF_BL  (3*TILE_B)
#define STAGE_B (4*TILE_B)          // 73728
#define SMEM_GEMM (2*STAGE_B)       // 147456

__global__ __launch_bounds__(256) void gemm_tc(
    const __nv_bfloat16* __restrict__ a_hi, const __nv_bfloat16* __restrict__ a_lo,
    const __nv_bfloat16* __restrict__ bt_hi, const __nv_bfloat16* __restrict__ bt_lo,
    float* __restrict__ C, int storeHeadMajor)
{
    extern __shared__ char smem[];
    const uint32_t sb = smem_u32(smem);
    const int tid  = threadIdx.x;
    const int wid  = tid >> 5;
    const int lane = tid & 31;
    const int bm   = blockIdx.y * 128;
    const int bn   = blockIdx.x * 128;

    const uint4* pAh = (const uint4*)a_hi;
    const uint4* pAl = (const uint4*)a_lo;
    const uint4* pBh = (const uint4*)bt_hi;
    const uint4* pBl = (const uint4*)bt_lo;

    // per-thread load geometry: g = tid + 256*i -> row g>>3, 16B-group g&7
    const int lrow = tid >> 3;        // row for i=0 (rows advance by 32 per i)
    const int lc8  = tid & 7;

    float acc[4][4][4];
#pragma unroll
    for (int mt = 0; mt < 4; mt++)
#pragma unroll
        for (int nt = 0; nt < 4; nt++)
#pragma unroll
            for (int e = 0; e < 4; e++) acc[mt][nt][e] = 0.f;

    // ldmatrix per-lane address components
    const int mbase = (wid & 1) * 64;
    const int nbase = (wid >> 1) * 32;
    const int aRow  = mbase + (lane & 15);
    const int aKoff = (lane >> 4) * 8;
    const int bRow  = nbase + (lane & 7) + ((lane >> 4) & 1) * 8;
    const int bKoff = ((lane >> 3) & 1) * 8;
    const uint32_t aOffBase = (uint32_t)((aRow * PADK + aKoff) * 2);
    const uint32_t bOffBase = (uint32_t)((bRow * PADK + bKoff) * 2);

    // issue chunk loads into stage st
    auto issue = [&](int c, int st) {
        const uint32_t stb = sb + (uint32_t)st * STAGE_B;
#pragma unroll
        for (int i = 0; i < 4; i++) {
            int row = lrow + i * 32;
            uint32_t so = stb + (uint32_t)((row * PADK + lc8 * 8) * 2);
            size_t ai = (size_t)(bm + row) * 128 + c * 8 + lc8;
            size_t bi = (size_t)(bn + row) * 128 + c * 8 + lc8;
            cp16(so + OFF_AH, pAh + ai);
            cp16(so + OFF_AL, pAl + ai);
            cp16(so + OFF_BH, pBh + bi);
            cp16(so + OFF_BL, pBl + bi);
        }
        CP_COMMIT();
    };

    issue(0, 0);

    for (int c = 0; c < 16; c++) {
        if (c < 15) issue(c + 1, (c + 1) & 1);
        if (c < 15) { CP_WAIT1(); } else { CP_WAIT0(); }
        __syncthreads();

        const uint32_t stb = sb + (uint32_t)(c & 1) * STAGE_B;
#pragma unroll
        for (int ks = 0; ks < 4; ks++) {
            const uint32_t kb = (uint32_t)(ks * 16 * 2);
            // B fragments: 2 x4 loads each for hi and lo (n-groups 0,1)
            uint32_t bh[8], bl[8];
            ldsm4(bh[0], bh[1], bh[2], bh[3], stb + OFF_BH + bOffBase + kb);
            ldsm4(bh[4], bh[5], bh[6], bh[7], stb + OFF_BH + bOffBase + kb + 16 * PADK * 2);
            ldsm4(bl[0], bl[1], bl[2], bl[3], stb + OFF_BL + bOffBase + kb);
            ldsm4(bl[4], bl[5], bl[6], bl[7], stb + OFF_BL + bOffBase + kb + 16 * PADK * 2);
#pragma unroll
            for (int mt = 0; mt < 4; mt++) {
                const uint32_t aoff = aOffBase + (uint32_t)(mt * 16 * PADK * 2) + kb;
                uint32_t ah[4], al[4];
                ldsm4(ah[0], ah[1], ah[2], ah[3], stb + OFF_AH + aoff);
                ldsm4(al[0], al[1], al[2], al[3], stb + OFF_AL + aoff);
#pragma unroll
                for (int nt = 0; nt < 4; nt++) {
                    const uint32_t* bfh = &bh[(nt & 1) ? ((nt >> 1) * 4 + 2) : ((nt >> 1) * 4)];
                    const uint32_t* bfl = &bl[(nt & 1) ? ((nt >> 1) * 4 + 2) : ((nt >> 1) * 4)];
                    mma_bf16(acc[mt][nt], ah, bfh);
                    mma_bf16(acc[mt][nt], ah, bfl);
                    mma_bf16(acc[mt][nt], al, bfh);
                }
            }
        }
        __syncthreads();
    }

    // epilogue: lane holds (r, c), (r, c+1), (r+8, c), (r+8, c+1) per (mt, nt)
    const int rl = lane >> 2;
    const int cl = (lane & 3) * 2;
#pragma unroll
    for (int mt = 0; mt < 4; mt++) {
#pragma unroll
        for (int nt = 0; nt < 4; nt++) {
            const int row0 = bm + mbase + mt * 16 + rl;
            const int colg = bn + nbase + nt * 8 + cl;
            float* cp0;
            float* cp1;
            if (!storeHeadMajor) {
                cp0 = C + (size_t)row0 * DD + colg;
                cp1 = cp0 + 8 * DD;
            } else {
                const int b = row0 >> 11, s = row0 & 2047;
                const int h = colg >> 6, dh0 = colg & 63;
                cp0 = C + (((size_t)(b * HH + h)) * SS + s) * DH + dh0;
                cp1 = cp0 + 8 * DH;   // row0+8 stays in same (b, s+8? no: s+8) — recompute
                const int row1 = row0 + 8;
                const int b1 = row1 >> 11, s1 = row1 & 2047;
                cp1 = C + (((size_t)(b1 * HH + h)) * SS + s1) * DH + dh0;
            }
            *(float2*)cp0 = make_float2(acc[mt][nt][0], acc[mt][nt][1]);
            *(float2*)cp1 = make_float2(acc[mt][nt][2], acc[mt][nt][3]);
        }
    }
}

// ---------------------------------------------------------------------------
// Attention (unchanged from R3): 4 queries/warp, 8 warps/block.
// ---------------------------------------------------------------------------
__global__ __launch_bounds__(256) void attn_kernel(
    const int* __restrict__ valid_lens_raw, float* __restrict__ out)
{
    __shared__ float4 q4[32 * 16];
    __shared__ float4 ks4[16 * 33];
    __shared__ float  vs[32 * 64];
    __shared__ float4 ps4[8 * 32];

    const int tid  = threadIdx.x;
    const int w    = tid >> 5;
    const int lane = tid & 31;
    const int bh   = blockIdx.y;
    const int b    = bh >> 4;
    const int h    = bh & 15;

    const int L = load_valid_len(valid_lens_raw, b);
    const bool uniform = (L == 0);
    const int Leff = uniform ? SS : L;
    const int q0 = blockIdx.x * 32;

#pragma unroll
    for (int i = 0; i < 2; i++) {
        int f4 = tid + i * 256;
        q4[f4] = *(const float4*)(g_q + ((size_t)bh * SS + q0 + (f4 >> 4)) * DH + (f4 & 15) * 4);
    }

    float m[4], l[4];
    float2 o[4];
#pragma unroll
    for (int qq = 0; qq < 4; qq++) {
        m[qq] = -INFINITY; l[qq] = 0.f; o[qq] = make_float2(0.f, 0.f);
    }

    const int nt = (Leff + 31) >> 5;
    for (int t = 0; t < nt; t++) {
        const int kb = t * 32;
        __syncthreads();
#pragma unroll
        for (int i = 0; i < 2; i++) {
            int f4 = tid + i * 256;
            int j  = f4 >> 4;
            int dq = f4 & 15;
            const size_t base = ((size_t)bh * SS + kb + j) * DH + dq * 4;
            ks4[dq * 33 + j] = *(const float4*)(g_k + base);
            *(float4*)(&vs[j * 64 + dq * 4]) = *(const float4*)(g_v + base);
        }
        __syncthreads();

        float s[4] = {0.f, 0.f, 0.f, 0.f};
        if (!uniform) {
#pragma unroll
            for (int dq = 0; dq < 16; dq++) {
                float4 kv = ks4[dq * 33 + lane];
#pragma unroll
                for (int qq = 0; qq < 4; qq++) {
                    float4 qv = q4[(w * 4 + qq) * 16 + dq];
                    s[qq] += qv.x * kv.x + qv.y * kv.y + qv.z * kv.z + qv.w * kv.w;
                }
            }
#pragma unroll
            for (int qq = 0; qq < 4; qq++) s[qq] *= 0.125f;
        }

        const bool valid = (kb + lane) < Leff;
        float p[4];
#pragma unroll
        for (int qq = 0; qq < 4; qq++) {
            float sv = valid ? s[qq] : -FLT_MAX;
#pragma unroll
            for (int off = 16; off > 0; off >>= 1)
                sv = fmaxf(sv, __shfl_xor_sync(0xffffffffu, sv, off));
            const float mn = fmaxf(m[qq], sv);
            p[qq] = valid ? __expf(s[qq] - mn) : 0.f;
            const float alpha = __expf(m[qq] - mn);
            float psum = p[qq];
#pragma unroll
            for (int off = 16; off > 0; off >>= 1)
                psum += __shfl_xor_sync(0xffffffffu, psum, off);
            l[qq] = l[qq] * alpha + psum;
            o[qq].x *= alpha; o[qq].y *= alpha;
            m[qq] = mn;
        }
        ps4[w * 32 + lane] = make_float4(p[0], p[1], p[2], p[3]);
        __syncwarp();

#pragma unroll 8
        for (int j = 0; j < 32; j++) {
            float4 pj = ps4[w * 32 + j];
            float2 vv = *(const float2*)&vs[j * 64 + lane * 2];
            o[0].x += pj.x * vv.x; o[0].y += pj.x * vv.y;
            o[1].x += pj.y * vv.x; o[1].y += pj.y * vv.y;
            o[2].x += pj.z * vv.x; o[2].y += pj.z * vv.y;
            o[3].x += pj.w * vv.x; o[3].y += pj.w * vv.y;
        }
    }

#pragma unroll
    for (int qq = 0; qq < 4; qq++) {
        const float inv = 1.f / l[qq];
        const int qi = q0 + w * 4 + qq;
        float* op = out + ((size_t)(b * SS + qi)) * DD + h * DH + lane * 2;
        op[0] = o[qq].x * inv;
        op[1] = o[qq].y * inv;
    }
}

// ---------------------------------------------------------------------------
extern "C" void kernel_launch(void* const* d_in, const int* in_sizes, int n_in,
                              void* d_out, int out_size)
{
    const float* Q  = (const float*)d_in[0];
    const float* Km = (const float*)d_in[1];
    const float* V  = (const float*)d_in[2];
    const int*   vl = (const int*)d_in[3];
    const float* Wq = (const float*)d_in[4];
    const float* Wk = (const float*)d_in[5];
    const float* Wv = (const float*)d_in[6];
    const float* Wo = (const float*)d_in[7];
    float* out = (float*)d_out;

    float *pq, *pk, *pv, *pa;
    cudaGetSymbolAddress((void**)&pq, g_q);
    cudaGetSymbolAddress((void**)&pk, g_k);
    cudaGetSymbolAddress((void**)&pv, g_v);
    cudaGetSymbolAddress((void**)&pa, g_att);

    __nv_bfloat16 *qh, *ql, *kh, *kl, *vh, *vvl, *ch, *cl, *wth, *wtl;
    cudaGetSymbolAddress((void**)&qh, g_qh);  cudaGetSymbolAddress((void**)&ql, g_ql);
    cudaGetSymbolAddress((void**)&kh, g_kh);  cudaGetSymbolAddress((void**)&kl, g_kl);
    cudaGetSymbolAddress((void**)&vh, g_vh);  cudaGetSymbolAddress((void**)&vvl, g_vl);
    cudaGetSymbolAddress((void**)&ch, g_ch);  cudaGetSymbolAddress((void**)&cl, g_cl);
    cudaGetSymbolAddress((void**)&wth, g_wth); cudaGetSymbolAddress((void**)&wtl, g_wtl);

    cudaFuncSetAttribute(gemm_tc, cudaFuncAttributeMaxDynamicSharedMemorySize, SMEM_GEMM);

    const int nblkSplit = (int)(NEL / 4 / 256);          // 8192
    split_kernel<<<nblkSplit, 256>>>((const float4*)Q,  (ushort4*)qh, (ushort4*)ql);
    split_kernel<<<nblkSplit, 256>>>((const float4*)Km, (ushort4*)kh, (ushort4*)kl);
    split_kernel<<<nblkSplit, 256>>>((const float4*)V,  (ushort4*)vh, (ushort4*)vvl);

    dim3 gW(32, 32), bW(32, 8);
    const float* Ws[4] = {Wq, Wk, Wv, Wo};
    for (int i = 0; i < 4; i++)
        wsplit_kernel<<<gW, bW>>>(Ws[i], wth + (size_t)i * DD * DD, wtl + (size_t)i * DD * DD);

    dim3 gG(DD / 128, MROWS / 128);                       // (8, 64)
    gemm_tc<<<gG, 256, SMEM_GEMM>>>(qh, ql, wth + 0 * (size_t)DD * DD, wtl + 0 * (size_t)DD * DD, pq, 1);
    gemm_tc<<<gG, 256, SMEM_GEMM>>>(kh, kl, wth + 1 * (size_t)DD * DD, wtl + 1 * (size_t)DD * DD, pk, 1);
    gemm_tc<<<gG, 256, SMEM_GEMM>>>(vh, vvl, wth + 2 * (size_t)DD * DD, wtl + 2 * (size_t)DD * DD, pv, 1);

    dim3 gAttn(SS / 32, BB * HH);                         // (64, 64)
    attn_kernel<<<gAttn, 256>>>(vl, pa);

    split_kernel<<<nblkSplit, 256>>>((const float4*)pa, (ushort4*)ch, (ushort4*)cl);
    gemm_tc<<<gG, 256, SMEM_GEMM>>>(ch, cl, wth + 3 * (size_t)DD * DD, wtl + 3 * (size_t)DD * DD, out, 0);
}

// round 6
// speedup vs baseline: 4.7791x; 2.0405x over previous
#include <cuda_runtime.h>
#include <cuda_bf16.h>
#include <math.h>
#include <float.h>
#include <stdint.h>

// Problem constants
#define BB   4
#define SS   2048
#define DD   1024
#define HH   16
#define DH   64
#define MROWS (BB*SS)      // 8192

// ---------------------------------------------------------------------------
// Scratch (allocation-free rule: __device__ globals)
// ---------------------------------------------------------------------------
#define NEL ((size_t)MROWS*DD)               // 8M elements
// input splits (row-major [8192,1024])
__device__ __align__(16) __nv_bfloat16 g_qh[NEL], g_ql[NEL];
__device__ __align__(16) __nv_bfloat16 g_kh[NEL], g_kl[NEL];
__device__ __align__(16) __nv_bfloat16 g_vh[NEL], g_vl[NEL];
// projected q/k/v splits, head-major [(b*H+h)*S + s][dh]
__device__ __align__(16) __nv_bfloat16 g_pqh[NEL], g_pql[NEL];
__device__ __align__(16) __nv_bfloat16 g_pkh[NEL], g_pkl[NEL];
__device__ __align__(16) __nv_bfloat16 g_pvh[NEL], g_pvl[NEL];
// attention output splits, concat layout [b*S+s][h*64+dh]
__device__ __align__(16) __nv_bfloat16 g_ch[NEL], g_cl[NEL];
// transposed weight splits [n][k]
__device__ __align__(16) __nv_bfloat16 g_wth[4][DD*DD], g_wtl[4][DD*DD];

// ---------------------------------------------------------------------------
// helpers
// ---------------------------------------------------------------------------
__device__ __forceinline__ uint32_t smem_u32(const void* p) {
    uint32_t a;
    asm("{ .reg .u64 t; cvta.to.shared.u64 t, %1; cvt.u32.u64 %0, t; }" : "=r"(a) : "l"(p));
    return a;
}
__device__ __forceinline__ void cp16(uint32_t dst, const void* src) {
    asm volatile("cp.async.cg.shared.global [%0], [%1], 16;" :: "r"(dst), "l"(src));
}
#define CP_COMMIT() asm volatile("cp.async.commit_group;" ::: "memory")
#define CP_WAIT1()  asm volatile("cp.async.wait_group 1;" ::: "memory")
#define CP_WAIT0()  asm volatile("cp.async.wait_group 0;" ::: "memory")

__device__ __forceinline__ void ldsm4(uint32_t& r0, uint32_t& r1, uint32_t& r2, uint32_t& r3,
                                      uint32_t addr) {
    asm volatile("ldmatrix.sync.aligned.m8n8.x4.shared.b16 {%0,%1,%2,%3}, [%4];"
                 : "=r"(r0), "=r"(r1), "=r"(r2), "=r"(r3) : "r"(addr));
}
__device__ __forceinline__ void ldsm4t(uint32_t& r0, uint32_t& r1, uint32_t& r2, uint32_t& r3,
                                       uint32_t addr) {
    asm volatile("ldmatrix.sync.aligned.m8n8.x4.trans.shared.b16 {%0,%1,%2,%3}, [%4];"
                 : "=r"(r0), "=r"(r1), "=r"(r2), "=r"(r3) : "r"(addr));
}
__device__ __forceinline__ void mma_bf16(float* c, const uint32_t* a, const uint32_t* b) {
    asm volatile(
        "mma.sync.aligned.m16n8k16.row.col.f32.bf16.bf16.f32 "
        "{%0,%1,%2,%3}, {%4,%5,%6,%7}, {%8,%9}, {%0,%1,%2,%3};"
        : "+f"(c[0]), "+f"(c[1]), "+f"(c[2]), "+f"(c[3])
        : "r"(a[0]), "r"(a[1]), "r"(a[2]), "r"(a[3]), "r"(b[0]), "r"(b[1]));
}
// pack two floats as bf16x2 {lo, hi}
__device__ __forceinline__ uint32_t pack_bf16(float lo, float hi) {
    __nv_bfloat162 t;
    t.x = __float2bfloat16_rn(lo);
    t.y = __float2bfloat16_rn(hi);
    return *reinterpret_cast<uint32_t*>(&t);
}

// ---------------------------------------------------------------------------
// valid_lens may physically be int32 (jax x64 disabled) or int64.
// ---------------------------------------------------------------------------
__device__ __forceinline__ int load_valid_len(const int* p, int b) {
    bool is64 = (p[1] == 0) && (p[3] == 0);
    int v = is64 ? p[2 * b] : p[b];
    if (v < 0) v = 0;
    if (v > SS) v = SS;
    return v;
}

// ---------------------------------------------------------------------------
// Elementwise fp32 -> (hi, lo) bf16 split. 4 elems/thread.
// ---------------------------------------------------------------------------
__global__ __launch_bounds__(256) void split_kernel(
    const float4* __restrict__ in, ushort4* __restrict__ hi, ushort4* __restrict__ lo)
{
    int i = blockIdx.x * 256 + threadIdx.x;
    float4 v = in[i];
    float f[4] = {v.x, v.y, v.z, v.w};
    unsigned short h[4], l[4];
#pragma unroll
    for (int j = 0; j < 4; j++) {
        __nv_bfloat16 hb = __float2bfloat16_rn(f[j]);
        __nv_bfloat16 lb = __float2bfloat16_rn(f[j] - __bfloat162float(hb));
        h[j] = __bfloat16_as_ushort(hb);
        l[j] = __bfloat16_as_ushort(lb);
    }
    hi[i] = make_ushort4(h[0], h[1], h[2], h[3]);
    lo[i] = make_ushort4(l[0], l[1], l[2], l[3]);
}

// ---------------------------------------------------------------------------
// W[k,n] -> wt_hi/wt_lo[n,k] bf16 (transpose + split)
// ---------------------------------------------------------------------------
__global__ __launch_bounds__(256) void wsplit_kernel(
    const float* __restrict__ W, __nv_bfloat16* __restrict__ th, __nv_bfloat16* __restrict__ tl)
{
    __shared__ float tile[32][33];
    const int tx = threadIdx.x, ty = threadIdx.y;      // (32, 8)
    const int bk = blockIdx.x * 32, bn = blockIdx.y * 32;
#pragma unroll
    for (int i = 0; i < 4; i++)
        tile[ty + 8 * i][tx] = W[(size_t)(bk + ty + 8 * i) * DD + bn + tx];
    __syncthreads();
#pragma unroll
    for (int i = 0; i < 4; i++) {
        float f = tile[tx][ty + 8 * i];
        __nv_bfloat16 hb = __float2bfloat16_rn(f);
        __nv_bfloat16 lb = __float2bfloat16_rn(f - __bfloat162float(hb));
        size_t o = (size_t)(bn + ty + 8 * i) * DD + bk + tx;
        th[o] = hb; tl[o] = lb;
    }
}

// ---------------------------------------------------------------------------
// Tensor-core GEMM (mma.sync bf16, 3-term split).
// mode 0: C fp32 row-major.  mode 2: bf16 hi/lo split, head-major.
// ---------------------------------------------------------------------------
#define PADK    72
#define TILE_B  (128*PADK*2)
#define OFF_AH  0
#define OFF_AL  (1*TILE_B)
#define OFF_BH  (2*TILE_B)
#define OFF_BL  (3*TILE_B)
#define STAGE_B (4*TILE_B)
#define SMEM_GEMM (2*STAGE_B)       // 147456

__global__ __launch_bounds__(256) void gemm_tc(
    const __nv_bfloat16* __restrict__ a_hi, const __nv_bfloat16* __restrict__ a_lo,
    const __nv_bfloat16* __restrict__ bt_hi, const __nv_bfloat16* __restrict__ bt_lo,
    float* __restrict__ C, __nv_bfloat16* __restrict__ Chi, __nv_bfloat16* __restrict__ Clo,
    int mode)
{
    extern __shared__ char smem[];
    const uint32_t sb = smem_u32(smem);
    const int tid  = threadIdx.x;
    const int wid  = tid >> 5;
    const int lane = tid & 31;
    const int bm   = blockIdx.y * 128;
    const int bn   = blockIdx.x * 128;

    const uint4* pAh = (const uint4*)a_hi;
    const uint4* pAl = (const uint4*)a_lo;
    const uint4* pBh = (const uint4*)bt_hi;
    const uint4* pBl = (const uint4*)bt_lo;

    const int lrow = tid >> 3;
    const int lc8  = tid & 7;

    float acc[4][4][4];
#pragma unroll
    for (int mt = 0; mt < 4; mt++)
#pragma unroll
        for (int nt = 0; nt < 4; nt++)
#pragma unroll
            for (int e = 0; e < 4; e++) acc[mt][nt][e] = 0.f;

    const int mbase = (wid & 1) * 64;
    const int nbase = (wid >> 1) * 32;
    const int aRow  = mbase + (lane & 15);
    const int aKoff = (lane >> 4) * 8;
    const int bRow  = nbase + (lane & 7) + ((lane >> 4) & 1) * 8;
    const int bKoff = ((lane >> 3) & 1) * 8;
    const uint32_t aOffBase = (uint32_t)((aRow * PADK + aKoff) * 2);
    const uint32_t bOffBase = (uint32_t)((bRow * PADK + bKoff) * 2);

    auto issue = [&](int c, int st) {
        const uint32_t stb = sb + (uint32_t)st * STAGE_B;
#pragma unroll
        for (int i = 0; i < 4; i++) {
            int row = lrow + i * 32;
            uint32_t so = stb + (uint32_t)((row * PADK + lc8 * 8) * 2);
            size_t ai = (size_t)(bm + row) * 128 + c * 8 + lc8;
            size_t bi = (size_t)(bn + row) * 128 + c * 8 + lc8;
            cp16(so + OFF_AH, pAh + ai);
            cp16(so + OFF_AL, pAl + ai);
            cp16(so + OFF_BH, pBh + bi);
            cp16(so + OFF_BL, pBl + bi);
        }
        CP_COMMIT();
    };

    issue(0, 0);

    for (int c = 0; c < 16; c++) {
        if (c < 15) issue(c + 1, (c + 1) & 1);
        if (c < 15) { CP_WAIT1(); } else { CP_WAIT0(); }
        __syncthreads();

        const uint32_t stb = sb + (uint32_t)(c & 1) * STAGE_B;
#pragma unroll
        for (int ks = 0; ks < 4; ks++) {
            const uint32_t kb = (uint32_t)(ks * 16 * 2);
            uint32_t bh[8], bl[8];
            ldsm4(bh[0], bh[1], bh[2], bh[3], stb + OFF_BH + bOffBase + kb);
            ldsm4(bh[4], bh[5], bh[6], bh[7], stb + OFF_BH + bOffBase + kb + 16 * PADK * 2);
            ldsm4(bl[0], bl[1], bl[2], bl[3], stb + OFF_BL + bOffBase + kb);
            ldsm4(bl[4], bl[5], bl[6], bl[7], stb + OFF_BL + bOffBase + kb + 16 * PADK * 2);
#pragma unroll
            for (int mt = 0; mt < 4; mt++) {
                const uint32_t aoff = aOffBase + (uint32_t)(mt * 16 * PADK * 2) + kb;
                uint32_t ah[4], al[4];
                ldsm4(ah[0], ah[1], ah[2], ah[3], stb + OFF_AH + aoff);
                ldsm4(al[0], al[1], al[2], al[3], stb + OFF_AL + aoff);
#pragma unroll
                for (int nt = 0; nt < 4; nt++) {
                    const uint32_t* bfh = &bh[(nt & 1) ? ((nt >> 1) * 4 + 2) : ((nt >> 1) * 4)];
                    const uint32_t* bfl = &bl[(nt & 1) ? ((nt >> 1) * 4 + 2) : ((nt >> 1) * 4)];
                    mma_bf16(acc[mt][nt], ah, bfh);
                    mma_bf16(acc[mt][nt], ah, bfl);
                    mma_bf16(acc[mt][nt], al, bfh);
                }
            }
        }
        __syncthreads();
    }

    const int rl = lane >> 2;
    const int cl = (lane & 3) * 2;
#pragma unroll
    for (int mt = 0; mt < 4; mt++) {
#pragma unroll
        for (int nt = 0; nt < 4; nt++) {
            const int row0 = bm + mbase + mt * 16 + rl;
            const int row1 = row0 + 8;
            const int colg = bn + nbase + nt * 8 + cl;
            if (mode == 0) {
                float* cp0 = C + (size_t)row0 * DD + colg;
                float* cp1 = C + (size_t)row1 * DD + colg;
                *(float2*)cp0 = make_float2(acc[mt][nt][0], acc[mt][nt][1]);
                *(float2*)cp1 = make_float2(acc[mt][nt][2], acc[mt][nt][3]);
            } else {
                const int h = colg >> 6, dh0 = colg & 63;
                const int b0 = row0 >> 11, s0 = row0 & 2047;
                const int b1 = row1 >> 11, s1 = row1 & 2047;
                size_t o0 = (((size_t)(b0 * HH + h)) * SS + s0) * DH + dh0;
                size_t o1 = (((size_t)(b1 * HH + h)) * SS + s1) * DH + dh0;
                float v0 = acc[mt][nt][0], v1 = acc[mt][nt][1];
                float v2 = acc[mt][nt][2], v3 = acc[mt][nt][3];
                float h0 = __bfloat162float(__float2bfloat16_rn(v0));
                float h1 = __bfloat162float(__float2bfloat16_rn(v1));
                float h2 = __bfloat162float(__float2bfloat16_rn(v2));
                float h3 = __bfloat162float(__float2bfloat16_rn(v3));
                *(uint32_t*)(Chi + o0) = pack_bf16(h0, h1);
                *(uint32_t*)(Clo + o0) = pack_bf16(v0 - h0, v1 - h1);
                *(uint32_t*)(Chi + o1) = pack_bf16(h2, h3);
                *(uint32_t*)(Clo + o1) = pack_bf16(v2 - h2, v3 - h3);
            }
        }
    }
}

// ---------------------------------------------------------------------------
// Flash attention with mma.sync bf16 (3-term split QK and PV).
// Block: 128 queries x one (b,h). 8 warps, warp = 16 query rows.
// Key tiles of 64; 2-stage cp.async pipeline for Kh/Kl/Vh/Vl.
// Output: bf16 hi/lo split in concat layout [b*S+s][h*64+dh].
// ---------------------------------------------------------------------------
#define ATQ  128
#define ATK  64
#define APAD 72
#define AT_TILE (ATK*APAD*2)          // 9216 bytes per K/V tile
#define AQ_OFF_H 0
#define AQ_OFF_L (ATQ*APAD*2)         // 18432
#define AST_BASE (2*ATQ*APAD*2)       // 36864
#define AST_B    (4*AT_TILE)          // 36864 per stage
#define AKH 0
#define AKL (1*AT_TILE)
#define AVH (2*AT_TILE)
#define AVL (3*AT_TILE)
#define SMEM_ATTN (AST_BASE + 2*AST_B)   // 110592

__global__ __launch_bounds__(256) void attn_tc(
    const int* __restrict__ valid_lens_raw,
    __nv_bfloat16* __restrict__ outh, __nv_bfloat16* __restrict__ outl)
{
    extern __shared__ char smem[];
    const uint32_t sb = smem_u32(smem);
    const int tid  = threadIdx.x;
    const int w    = tid >> 5;
    const int lane = tid & 31;
    const int bh   = blockIdx.y;
    const int b    = bh >> 4;
    const int h    = bh & 15;
    const int qbase = blockIdx.x * ATQ;

    const int L = load_valid_len(valid_lens_raw, b);
    const bool uniform = (L == 0);
    const int Leff = uniform ? SS : L;
    const int ntiles = (Leff + ATK - 1) >> 6;

    const uint4* pQh = (const uint4*)g_pqh;
    const uint4* pQl = (const uint4*)g_pql;
    const uint4* pKh = (const uint4*)g_pkh;
    const uint4* pKl = (const uint4*)g_pkl;
    const uint4* pVh = (const uint4*)g_pvh;
    const uint4* pVl = (const uint4*)g_pvl;

    // ---- issue Q load (hi+lo): 128 rows x 8 groups, 2 arrays ----
    {
#pragma unroll
        for (int i = 0; i < 4; i++) {
            int g = tid + i * 256;            // 0..1023
            int row = g >> 3, c8 = g & 7;
            size_t gi = ((size_t)bh * SS + qbase + row) * 8 + c8;
            uint32_t so = (uint32_t)((row * APAD + c8 * 8) * 2);
            cp16(sb + AQ_OFF_H + so, pQh + gi);
            cp16(sb + AQ_OFF_L + so, pQl + gi);
        }
        CP_COMMIT();
    }

    auto issueKV = [&](int t, int st) {
        const uint32_t stb = sb + AST_BASE + (uint32_t)st * AST_B;
        const int kb = t * ATK;
#pragma unroll
        for (int i = 0; i < 2; i++) {
            int g = tid + i * 256;            // 0..511
            int row = g >> 3, c8 = g & 7;
            size_t gi = ((size_t)bh * SS + kb + row) * 8 + c8;
            uint32_t so = (uint32_t)((row * APAD + c8 * 8) * 2);
            cp16(stb + AKH + so, pKh + gi);
            cp16(stb + AKL + so, pKl + gi);
            cp16(stb + AVH + so, pVh + gi);
            cp16(stb + AVL + so, pVl + gi);
        }
        CP_COMMIT();
    };

    issueKV(0, 0);
    CP_WAIT1();            // Q group complete
    __syncthreads();

    // ---- Q fragments into registers (held across all tiles) ----
    const int gid = lane >> 2;
    const int qrl = lane & 3;
    uint32_t qfh[4][4], qfl[4][4];
    {
        const int aRow = w * 16 + (lane & 15);
        const uint32_t aoff0 = (uint32_t)((aRow * APAD + (lane >> 4) * 8) * 2);
#pragma unroll
        for (int ks = 0; ks < 4; ks++) {
            uint32_t kb = (uint32_t)(ks * 16 * 2);
            ldsm4(qfh[ks][0], qfh[ks][1], qfh[ks][2], qfh[ks][3], sb + AQ_OFF_H + aoff0 + kb);
            ldsm4(qfl[ks][0], qfl[ks][1], qfl[ks][2], qfl[ks][3], sb + AQ_OFF_L + aoff0 + kb);
        }
    }

    float O[8][4];
#pragma unroll
    for (int nt = 0; nt < 8; nt++)
#pragma unroll
        for (int e = 0; e < 4; e++) O[nt][e] = 0.f;
    float m0 = -FLT_MAX, m1 = -FLT_MAX, l0 = 0.f, l1 = 0.f;

    // K b-frag lane geometry (same as GEMM B)
    const int kRow = (lane & 7) + ((lane >> 4) & 1) * 8;
    const int kKof = ((lane >> 3) & 1) * 8;
    // V trans lane geometry
    const int vRow = lane & 15;
    const int vCol = (lane >> 4) * 8;

    for (int t = 0; t < ntiles; t++) {
        if (t + 1 < ntiles) issueKV(t + 1, (t + 1) & 1);
        if (t + 1 < ntiles) { CP_WAIT1(); } else { CP_WAIT0(); }
        __syncthreads();

        const uint32_t stb = sb + AST_BASE + (uint32_t)(t & 1) * AST_B;

        // ---- scores S = Q K^T ----
        float c[8][4];
#pragma unroll
        for (int nt = 0; nt < 8; nt++)
#pragma unroll
            for (int e = 0; e < 4; e++) c[nt][e] = 0.f;

        if (!uniform) {
#pragma unroll
            for (int ks = 0; ks < 4; ks++) {
                const uint32_t kb = (uint32_t)(ks * 16 * 2);
#pragma unroll
                for (int g = 0; g < 4; g++) {
                    const uint32_t boff = (uint32_t)(((g * 16 + kRow) * APAD + kKof) * 2) + kb;
                    uint32_t kh4[4], kl4[4];
                    ldsm4(kh4[0], kh4[1], kh4[2], kh4[3], stb + AKH + boff);
                    ldsm4(kl4[0], kl4[1], kl4[2], kl4[3], stb + AKL + boff);
                    mma_bf16(c[2 * g],     qfh[ks], kh4 + 0);
                    mma_bf16(c[2 * g],     qfh[ks], kl4 + 0);
                    mma_bf16(c[2 * g],     qfl[ks], kh4 + 0);
                    mma_bf16(c[2 * g + 1], qfh[ks], kh4 + 2);
                    mma_bf16(c[2 * g + 1], qfh[ks], kl4 + 2);
                    mma_bf16(c[2 * g + 1], qfl[ks], kh4 + 2);
                }
            }
        }

        // ---- scale + mask ----
        const int tilebase = t * ATK;
        const bool partial = (tilebase + ATK) > Leff;
#pragma unroll
        for (int nt = 0; nt < 8; nt++) {
#pragma unroll
            for (int e = 0; e < 4; e++) {
                float s = c[nt][e] * 0.125f;
                if (partial) {
                    int key = tilebase + nt * 8 + qrl * 2 + (e & 1);
                    if (key >= Leff) s = -FLT_MAX;
                }
                c[nt][e] = s;
            }
        }

        // ---- online softmax ----
        float rm0 = -FLT_MAX, rm1 = -FLT_MAX;
#pragma unroll
        for (int nt = 0; nt < 8; nt++) {
            rm0 = fmaxf(rm0, fmaxf(c[nt][0], c[nt][1]));
            rm1 = fmaxf(rm1, fmaxf(c[nt][2], c[nt][3]));
        }
#pragma unroll
        for (int off = 1; off <= 2; off <<= 1) {
            rm0 = fmaxf(rm0, __shfl_xor_sync(0xffffffffu, rm0, off));
            rm1 = fmaxf(rm1, __shfl_xor_sync(0xffffffffu, rm1, off));
        }
        const float mn0 = fmaxf(m0, rm0);
        const float mn1 = fmaxf(m1, rm1);
        const float al0 = __expf(m0 - mn0);
        const float al1 = __expf(m1 - mn1);
        m0 = mn0; m1 = mn1;

        float ps0 = 0.f, ps1 = 0.f;
        uint32_t ph01[8], ph23[8], pl01[8], pl23[8];
#pragma unroll
        for (int nt = 0; nt < 8; nt++) {
            float p0 = __expf(c[nt][0] - mn0);
            float p1 = __expf(c[nt][1] - mn0);
            float p2 = __expf(c[nt][2] - mn1);
            float p3 = __expf(c[nt][3] - mn1);
            ps0 += p0 + p1; ps1 += p2 + p3;
            float h0 = __bfloat162float(__float2bfloat16_rn(p0));
            float h1 = __bfloat162float(__float2bfloat16_rn(p1));
            float h2 = __bfloat162float(__float2bfloat16_rn(p2));
            float h3 = __bfloat162float(__float2bfloat16_rn(p3));
            ph01[nt] = pack_bf16(h0, h1);
            ph23[nt] = pack_bf16(h2, h3);
            pl01[nt] = pack_bf16(p0 - h0, p1 - h1);
            pl23[nt] = pack_bf16(p2 - h2, p3 - h3);
        }
#pragma unroll
        for (int off = 1; off <= 2; off <<= 1) {
            ps0 += __shfl_xor_sync(0xffffffffu, ps0, off);
            ps1 += __shfl_xor_sync(0xffffffffu, ps1, off);
        }
        l0 = l0 * al0 + ps0;
        l1 = l1 * al1 + ps1;
#pragma unroll
        for (int nt = 0; nt < 8; nt++) {
            O[nt][0] *= al0; O[nt][1] *= al0;
            O[nt][2] *= al1; O[nt][3] *= al1;
        }

        // ---- O += P V ----
#pragma unroll
        for (int tk = 0; tk < 4; tk++) {
            uint32_t ah[4] = {ph01[2 * tk], ph23[2 * tk], ph01[2 * tk + 1], ph23[2 * tk + 1]};
            uint32_t alr[4] = {pl01[2 * tk], pl23[2 * tk], pl01[2 * tk + 1], pl23[2 * tk + 1]};
#pragma unroll
            for (int g = 0; g < 4; g++) {
                const uint32_t voff = (uint32_t)(((tk * 16 + vRow) * APAD + g * 16 + vCol) * 2);
                uint32_t vh4[4], vl4[4];
                ldsm4t(vh4[0], vh4[1], vh4[2], vh4[3], stb + AVH + voff);
                ldsm4t(vl4[0], vl4[1], vl4[2], vl4[3], stb + AVL + voff);
                mma_bf16(O[2 * g],     ah,  vh4 + 0);
                mma_bf16(O[2 * g],     ah,  vl4 + 0);
                mma_bf16(O[2 * g],     alr, vh4 + 0);
                mma_bf16(O[2 * g + 1], ah,  vh4 + 2);
                mma_bf16(O[2 * g + 1], ah,  vl4 + 2);
                mma_bf16(O[2 * g + 1], alr, vh4 + 2);
            }
        }
        __syncthreads();
    }

    // ---- epilogue: normalize, split bf16, store concat layout ----
    const float inv0 = 1.f / l0;
    const float inv1 = 1.f / l1;
    const int q0g = qbase + w * 16 + gid;
    const int q1g = q0g + 8;
#pragma unroll
    for (int nt = 0; nt < 8; nt++) {
        const int col = h * 64 + nt * 8 + qrl * 2;
        size_t o0 = ((size_t)(b * SS + q0g)) * DD + col;
        size_t o1 = ((size_t)(b * SS + q1g)) * DD + col;
        float v0 = O[nt][0] * inv0, v1 = O[nt][1] * inv0;
        float v2 = O[nt][2] * inv1, v3 = O[nt][3] * inv1;
        float h0 = __bfloat162float(__float2bfloat16_rn(v0));
        float h1 = __bfloat162float(__float2bfloat16_rn(v1));
        float h2 = __bfloat162float(__float2bfloat16_rn(v2));
        float h3 = __bfloat162float(__float2bfloat16_rn(v3));
        *(uint32_t*)(outh + o0) = pack_bf16(h0, h1);
        *(uint32_t*)(outl + o0) = pack_bf16(v0 - h0, v1 - h1);
        *(uint32_t*)(outh + o1) = pack_bf16(h2, h3);
        *(uint32_t*)(outl + o1) = pack_bf16(v2 - h2, v3 - h3);
    }
}

// ---------------------------------------------------------------------------
extern "C" void kernel_launch(void* const* d_in, const int* in_sizes, int n_in,
                              void* d_out, int out_size)
{
    const float* Q  = (const float*)d_in[0];
    const float* Km = (const float*)d_in[1];
    const float* V  = (const float*)d_in[2];
    const int*   vl = (const int*)d_in[3];
    const float* Wq = (const float*)d_in[4];
    const float* Wk = (const float*)d_in[5];
    const float* Wv = (const float*)d_in[6];
    const float* Wo = (const float*)d_in[7];
    float* out = (float*)d_out;

    __nv_bfloat16 *qh, *ql, *kh, *kl, *vh, *vvl;
    __nv_bfloat16 *pqh, *pql, *pkh, *pkl, *pvh, *pvl, *ch, *cl, *wth, *wtl;
    cudaGetSymbolAddress((void**)&qh, g_qh);   cudaGetSymbolAddress((void**)&ql, g_ql);
    cudaGetSymbolAddress((void**)&kh, g_kh);   cudaGetSymbolAddress((void**)&kl, g_kl);
    cudaGetSymbolAddress((void**)&vh, g_vh);   cudaGetSymbolAddress((void**)&vvl, g_vl);
    cudaGetSymbolAddress((void**)&pqh, g_pqh); cudaGetSymbolAddress((void**)&pql, g_pql);
    cudaGetSymbolAddress((void**)&pkh, g_pkh); cudaGetSymbolAddress((void**)&pkl, g_pkl);
    cudaGetSymbolAddress((void**)&pvh, g_pvh); cudaGetSymbolAddress((void**)&pvl, g_pvl);
    cudaGetSymbolAddress((void**)&ch, g_ch);   cudaGetSymbolAddress((void**)&cl, g_cl);
    cudaGetSymbolAddress((void**)&wth, g_wth); cudaGetSymbolAddress((void**)&wtl, g_wtl);

    cudaFuncSetAttribute(gemm_tc, cudaFuncAttributeMaxDynamicSharedMemorySize, SMEM_GEMM);
    cudaFuncSetAttribute(attn_tc, cudaFuncAttributeMaxDynamicSharedMemorySize, SMEM_ATTN);

    const int nblkSplit = (int)(NEL / 4 / 256);          // 8192
    split_kernel<<<nblkSplit, 256>>>((const float4*)Q,  (ushort4*)qh, (ushort4*)ql);
    split_kernel<<<nblkSplit, 256>>>((const float4*)Km, (ushort4*)kh, (ushort4*)kl);
    split_kernel<<<nblkSplit, 256>>>((const float4*)V,  (ushort4*)vh, (ushort4*)vvl);

    dim3 gW(32, 32), bW(32, 8);
    const float* Ws[4] = {Wq, Wk, Wv, Wo};
    for (int i = 0; i < 4; i++)
        wsplit_kernel<<<gW, bW>>>(Ws[i], wth + (size_t)i * DD * DD, wtl + (size_t)i * DD * DD);

    dim3 gG(DD / 128, MROWS / 128);                       // (8, 64)
    gemm_tc<<<gG, 256, SMEM_GEMM>>>(qh, ql, wth + 0 * (size_t)DD * DD, wtl + 0 * (size_t)DD * DD,
                                    nullptr, pqh, pql, 2);
    gemm_tc<<<gG, 256, SMEM_GEMM>>>(kh, kl, wth + 1 * (size_t)DD * DD, wtl + 1 * (size_t)DD * DD,
                                    nullptr, pkh, pkl, 2);
    gemm_tc<<<gG, 256, SMEM_GEMM>>>(vh, vvl, wth + 2 * (size_t)DD * DD, wtl + 2 * (size_t)DD * DD,
                                    nullptr, pvh, pvl, 2);

    dim3 gAttn(SS / ATQ, BB * HH);                        // (16, 64)
    attn_tc<<<gAttn, 256, SMEM_ATTN>>>(vl, ch, cl);

    gemm_tc<<<gG, 256, SMEM_GEMM>>>(ch, cl, wth + 3 * (size_t)DD * DD, wtl + 3 * (size_t)DD * DD,
                                    out, nullptr, nullptr, 0);
}

// round 7
// speedup vs baseline: 6.5836x; 1.3776x over previous
#include <cuda_runtime.h>
#include <cuda_fp16.h>
#include <math.h>
#include <float.h>
#include <stdint.h>

// Problem constants
#define BB   4
#define SS   2048
#define DD   1024
#define HH   16
#define DH   64
#define MROWS (BB*SS)      // 8192

// ---------------------------------------------------------------------------
// Scratch (allocation-free rule: __device__ globals)
// ---------------------------------------------------------------------------
#define NEL ((size_t)MROWS*DD)               // 8M elements
// input splits (row-major [8192,1024]) — A operands of projection GEMMs
__device__ __align__(16) __half g_qh[NEL], g_ql[NEL];
__device__ __align__(16) __half g_kh[NEL], g_kl[NEL];
__device__ __align__(16) __half g_vh[NEL], g_vl[NEL];
// projected q (hi+lo) / k / v (single), head-major [(b*H+h)*S + s][dh]
__device__ __align__(16) __half g_pqh[NEL], g_pql[NEL];
__device__ __align__(16) __half g_pk[NEL];
__device__ __align__(16) __half g_pv[NEL];
// attention output splits, concat layout [b*S+s][h*64+dh]
__device__ __align__(16) __half g_ch[NEL], g_cl[NEL];
// transposed weights [n][k], single fp16
__device__ __align__(16) __half g_wt[4][DD*DD];

// ---------------------------------------------------------------------------
// helpers
// ---------------------------------------------------------------------------
__device__ __forceinline__ uint32_t smem_u32(const void* p) {
    uint32_t a;
    asm("{ .reg .u64 t; cvta.to.shared.u64 t, %1; cvt.u32.u64 %0, t; }" : "=r"(a) : "l"(p));
    return a;
}
__device__ __forceinline__ void cp16(uint32_t dst, const void* src) {
    asm volatile("cp.async.cg.shared.global [%0], [%1], 16;" :: "r"(dst), "l"(src));
}
#define CP_COMMIT() asm volatile("cp.async.commit_group;" ::: "memory")
#define CP_WAIT1()  asm volatile("cp.async.wait_group 1;" ::: "memory")
#define CP_WAIT0()  asm volatile("cp.async.wait_group 0;" ::: "memory")

__device__ __forceinline__ void ldsm4(uint32_t& r0, uint32_t& r1, uint32_t& r2, uint32_t& r3,
                                      uint32_t addr) {
    asm volatile("ldmatrix.sync.aligned.m8n8.x4.shared.b16 {%0,%1,%2,%3}, [%4];"
                 : "=r"(r0), "=r"(r1), "=r"(r2), "=r"(r3) : "r"(addr));
}
__device__ __forceinline__ void ldsm4t(uint32_t& r0, uint32_t& r1, uint32_t& r2, uint32_t& r3,
                                       uint32_t addr) {
    asm volatile("ldmatrix.sync.aligned.m8n8.x4.trans.shared.b16 {%0,%1,%2,%3}, [%4];"
                 : "=r"(r0), "=r"(r1), "=r"(r2), "=r"(r3) : "r"(addr));
}
__device__ __forceinline__ void mma_f16(float* c, const uint32_t* a, const uint32_t* b) {
    asm volatile(
        "mma.sync.aligned.m16n8k16.row.col.f32.f16.f16.f32 "
        "{%0,%1,%2,%3}, {%4,%5,%6,%7}, {%8,%9}, {%0,%1,%2,%3};"
        : "+f"(c[0]), "+f"(c[1]), "+f"(c[2]), "+f"(c[3])
        : "r"(a[0]), "r"(a[1]), "r"(a[2]), "r"(a[3]), "r"(b[0]), "r"(b[1]));
}
// pack two floats as fp16x2 {lo, hi}
__device__ __forceinline__ uint32_t pack_f16(float lo, float hi) {
    __half2 t;
    t.x = __float2half_rn(lo);
    t.y = __float2half_rn(hi);
    return *reinterpret_cast<uint32_t*>(&t);
}

// ---------------------------------------------------------------------------
// valid_lens may physically be int32 (jax x64 disabled) or int64.
// ---------------------------------------------------------------------------
__device__ __forceinline__ int load_valid_len(const int* p, int b) {
    bool is64 = (p[1] == 0) && (p[3] == 0);
    int v = is64 ? p[2 * b] : p[b];
    if (v < 0) v = 0;
    if (v > SS) v = SS;
    return v;
}

// ---------------------------------------------------------------------------
// Elementwise fp32 -> (hi, lo) fp16 split. 4 elems/thread.
// ---------------------------------------------------------------------------
__global__ __launch_bounds__(256) void split_kernel(
    const float4* __restrict__ in, ushort4* __restrict__ hi, ushort4* __restrict__ lo)
{
    int i = blockIdx.x * 256 + threadIdx.x;
    float4 v = in[i];
    float f[4] = {v.x, v.y, v.z, v.w};
    unsigned short h[4], l[4];
#pragma unroll
    for (int j = 0; j < 4; j++) {
        __half hb = __float2half_rn(f[j]);
        __half lb = __float2half_rn(f[j] - __half2float(hb));
        h[j] = __half_as_ushort(hb);
        l[j] = __half_as_ushort(lb);
    }
    hi[i] = make_ushort4(h[0], h[1], h[2], h[3]);
    lo[i] = make_ushort4(l[0], l[1], l[2], l[3]);
}

// ---------------------------------------------------------------------------
// W[k,n] -> wt[n,k] fp16 (transpose + single rounding)
// ---------------------------------------------------------------------------
__global__ __launch_bounds__(256) void wsplit_kernel(
    const float* __restrict__ W, __half* __restrict__ th)
{
    __shared__ float tile[32][33];
    const int tx = threadIdx.x, ty = threadIdx.y;      // (32, 8)
    const int bk = blockIdx.x * 32, bn = blockIdx.y * 32;
#pragma unroll
    for (int i = 0; i < 4; i++)
        tile[ty + 8 * i][tx] = W[(size_t)(bk + ty + 8 * i) * DD + bn + tx];
    __syncthreads();
#pragma unroll
    for (int i = 0; i < 4; i++) {
        float f = tile[tx][ty + 8 * i];
        th[(size_t)(bn + ty + 8 * i) * DD + bk + tx] = __float2half_rn(f);
    }
}

// ---------------------------------------------------------------------------
// Tensor-core GEMM (mma.sync fp16, 2-term split: Ah*Bh + Al*Bh).
// mode 0: C fp32 row-major.
// mode 2: fp16 hi/lo split, head-major (q projection).
// mode 3: fp16 single, head-major (k/v projection).
// ---------------------------------------------------------------------------
#define PADK    72
#define TILE_B  (128*PADK*2)        // 18432
#define OFF_AH  0
#define OFF_AL  (1*TILE_B)
#define OFF_BH  (2*TILE_B)
#define STAGE_B (3*TILE_B)          // 55296
#define SMEM_GEMM (2*STAGE_B)       // 110592

__global__ __launch_bounds__(256) void gemm_tc(
    const __half* __restrict__ a_hi, const __half* __restrict__ a_lo,
    const __half* __restrict__ bt_hi,
    float* __restrict__ C, __half* __restrict__ Chi, __half* __restrict__ Clo,
    int mode)
{
    extern __shared__ char smem[];
    const uint32_t sb = smem_u32(smem);
    const int tid  = threadIdx.x;
    const int wid  = tid >> 5;
    const int lane = tid & 31;
    const int bm   = blockIdx.y * 128;
    const int bn   = blockIdx.x * 128;

    const uint4* pAh = (const uint4*)a_hi;
    const uint4* pAl = (const uint4*)a_lo;
    const uint4* pBh = (const uint4*)bt_hi;

    const int lrow = tid >> 3;
    const int lc8  = tid & 7;

    float acc[4][4][4];
#pragma unroll
    for (int mt = 0; mt < 4; mt++)
#pragma unroll
        for (int nt = 0; nt < 4; nt++)
#pragma unroll
            for (int e = 0; e < 4; e++) acc[mt][nt][e] = 0.f;

    const int mbase = (wid & 1) * 64;
    const int nbase = (wid >> 1) * 32;
    const int aRow  = mbase + (lane & 15);
    const int aKoff = (lane >> 4) * 8;
    const int bRow  = nbase + (lane & 7) + ((lane >> 4) & 1) * 8;
    const int bKoff = ((lane >> 3) & 1) * 8;
    const uint32_t aOffBase = (uint32_t)((aRow * PADK + aKoff) * 2);
    const uint32_t bOffBase = (uint32_t)((bRow * PADK + bKoff) * 2);

    auto issue = [&](int c, int st) {
        const uint32_t stb = sb + (uint32_t)st * STAGE_B;
#pragma unroll
        for (int i = 0; i < 4; i++) {
            int row = lrow + i * 32;
            uint32_t so = stb + (uint32_t)((row * PADK + lc8 * 8) * 2);
            size_t ai = (size_t)(bm + row) * 128 + c * 8 + lc8;
            size_t bi = (size_t)(bn + row) * 128 + c * 8 + lc8;
            cp16(so + OFF_AH, pAh + ai);
            cp16(so + OFF_AL, pAl + ai);
            cp16(so + OFF_BH, pBh + bi);
        }
        CP_COMMIT();
    };

    issue(0, 0);

    for (int c = 0; c < 16; c++) {
        if (c < 15) issue(c + 1, (c + 1) & 1);
        if (c < 15) { CP_WAIT1(); } else { CP_WAIT0(); }
        __syncthreads();

        const uint32_t stb = sb + (uint32_t)(c & 1) * STAGE_B;
#pragma unroll
        for (int ks = 0; ks < 4; ks++) {
            const uint32_t kb = (uint32_t)(ks * 16 * 2);
            uint32_t bh[8];
            ldsm4(bh[0], bh[1], bh[2], bh[3], stb + OFF_BH + bOffBase + kb);
            ldsm4(bh[4], bh[5], bh[6], bh[7], stb + OFF_BH + bOffBase + kb + 16 * PADK * 2);
#pragma unroll
            for (int mt = 0; mt < 4; mt++) {
                const uint32_t aoff = aOffBase + (uint32_t)(mt * 16 * PADK * 2) + kb;
                uint32_t ah[4], al[4];
                ldsm4(ah[0], ah[1], ah[2], ah[3], stb + OFF_AH + aoff);
                ldsm4(al[0], al[1], al[2], al[3], stb + OFF_AL + aoff);
#pragma unroll
                for (int nt = 0; nt < 4; nt++) {
                    const uint32_t* bfh = &bh[(nt & 1) ? ((nt >> 1) * 4 + 2) : ((nt >> 1) * 4)];
                    mma_f16(acc[mt][nt], ah, bfh);
                    mma_f16(acc[mt][nt], al, bfh);
                }
            }
        }
        __syncthreads();
    }

    const int rl = lane >> 2;
    const int cl = (lane & 3) * 2;
#pragma unroll
    for (int mt = 0; mt < 4; mt++) {
#pragma unroll
        for (int nt = 0; nt < 4; nt++) {
            const int row0 = bm + mbase + mt * 16 + rl;
            const int row1 = row0 + 8;
            const int colg = bn + nbase + nt * 8 + cl;
            float v0 = acc[mt][nt][0], v1 = acc[mt][nt][1];
            float v2 = acc[mt][nt][2], v3 = acc[mt][nt][3];
            if (mode == 0) {
                *(float2*)(C + (size_t)row0 * DD + colg) = make_float2(v0, v1);
                *(float2*)(C + (size_t)row1 * DD + colg) = make_float2(v2, v3);
            } else {
                const int h = colg >> 6, dh0 = colg & 63;
                const int b0 = row0 >> 11, s0 = row0 & 2047;
                const int b1 = row1 >> 11, s1 = row1 & 2047;
                size_t o0 = (((size_t)(b0 * HH + h)) * SS + s0) * DH + dh0;
                size_t o1 = (((size_t)(b1 * HH + h)) * SS + s1) * DH + dh0;
                if (mode == 3) {
                    *(uint32_t*)(Chi + o0) = pack_f16(v0, v1);
                    *(uint32_t*)(Chi + o1) = pack_f16(v2, v3);
                } else {
                    float h0 = __half2float(__float2half_rn(v0));
                    float h1 = __half2float(__float2half_rn(v1));
                    float h2 = __half2float(__float2half_rn(v2));
                    float h3 = __half2float(__float2half_rn(v3));
                    *(uint32_t*)(Chi + o0) = pack_f16(h0, h1);
                    *(uint32_t*)(Clo + o0) = pack_f16(v0 - h0, v1 - h1);
                    *(uint32_t*)(Chi + o1) = pack_f16(h2, h3);
                    *(uint32_t*)(Clo + o1) = pack_f16(v2 - h2, v3 - h3);
                }
            }
        }
    }
}

// ---------------------------------------------------------------------------
// Flash attention with mma.sync fp16.
// QK: Qh*Kh + Ql*Kh (K single fp16). PV: Ph*Vh + Pl*Vh (V single fp16).
// Block: 128 queries x one (b,h). 8 warps. Key tiles of 64, 2-stage pipeline.
// Output: fp16 hi/lo split in concat layout [b*S+s][h*64+dh].
// ---------------------------------------------------------------------------
#define ATQ  128
#define ATK  64
#define APAD 72
#define AT_TILE (ATK*APAD*2)          // 9216
#define AQ_OFF_H 0
#define AQ_OFF_L (ATQ*APAD*2)         // 18432
#define AST_BASE (2*ATQ*APAD*2)       // 36864
#define AST_B    (2*AT_TILE)          // 18432 per stage (K, V)
#define AKH 0
#define AVH (1*AT_TILE)
#define SMEM_ATTN (AST_BASE + 2*AST_B)   // 73728

__global__ __launch_bounds__(256) void attn_tc(
    const int* __restrict__ valid_lens_raw,
    __half* __restrict__ outh, __half* __restrict__ outl)
{
    extern __shared__ char smem[];
    const uint32_t sb = smem_u32(smem);
    const int tid  = threadIdx.x;
    const int w    = tid >> 5;
    const int lane = tid & 31;
    const int bh   = blockIdx.y;
    const int b    = bh >> 4;
    const int h    = bh & 15;
    const int qbase = blockIdx.x * ATQ;

    const int L = load_valid_len(valid_lens_raw, b);
    const bool uniform = (L == 0);
    const int Leff = uniform ? SS : L;
    const int ntiles = (Leff + ATK - 1) >> 6;

    const uint4* pQh = (const uint4*)g_pqh;
    const uint4* pQl = (const uint4*)g_pql;
    const uint4* pK  = (const uint4*)g_pk;
    const uint4* pV  = (const uint4*)g_pv;

    // ---- issue Q load (hi+lo) ----
    {
#pragma unroll
        for (int i = 0; i < 4; i++) {
            int g = tid + i * 256;            // 0..1023
            int row = g >> 3, c8 = g & 7;
            size_t gi = ((size_t)bh * SS + qbase + row) * 8 + c8;
            uint32_t so = (uint32_t)((row * APAD + c8 * 8) * 2);
            cp16(sb + AQ_OFF_H + so, pQh + gi);
            cp16(sb + AQ_OFF_L + so, pQl + gi);
        }
        CP_COMMIT();
    }

    auto issueKV = [&](int t, int st) {
        const uint32_t stb = sb + AST_BASE + (uint32_t)st * AST_B;
        const int kb = t * ATK;
#pragma unroll
        for (int i = 0; i < 2; i++) {
            int g = tid + i * 256;            // 0..511
            int row = g >> 3, c8 = g & 7;
            size_t gi = ((size_t)bh * SS + kb + row) * 8 + c8;
            uint32_t so = (uint32_t)((row * APAD + c8 * 8) * 2);
            cp16(stb + AKH + so, pK + gi);
            cp16(stb + AVH + so, pV + gi);
        }
        CP_COMMIT();
    };

    issueKV(0, 0);
    CP_WAIT1();            // Q group complete
    __syncthreads();

    // ---- Q fragments into registers ----
    const int gid = lane >> 2;
    const int qrl = lane & 3;
    uint32_t qfh[4][4], qfl[4][4];
    {
        const int aRow = w * 16 + (lane & 15);
        const uint32_t aoff0 = (uint32_t)((aRow * APAD + (lane >> 4) * 8) * 2);
#pragma unroll
        for (int ks = 0; ks < 4; ks++) {
            uint32_t kb = (uint32_t)(ks * 16 * 2);
            ldsm4(qfh[ks][0], qfh[ks][1], qfh[ks][2], qfh[ks][3], sb + AQ_OFF_H + aoff0 + kb);
            ldsm4(qfl[ks][0], qfl[ks][1], qfl[ks][2], qfl[ks][3], sb + AQ_OFF_L + aoff0 + kb);
        }
    }

    float O[8][4];
#pragma unroll
    for (int nt = 0; nt < 8; nt++)
#pragma unroll
        for (int e = 0; e < 4; e++) O[nt][e] = 0.f;
    float m0 = -FLT_MAX, m1 = -FLT_MAX, l0 = 0.f, l1 = 0.f;

    const int kRow = (lane & 7) + ((lane >> 4) & 1) * 8;
    const int kKof = ((lane >> 3) & 1) * 8;
    const int vRow = lane & 15;
    const int vCol = (lane >> 4) * 8;

    for (int t = 0; t < ntiles; t++) {
        if (t + 1 < ntiles) issueKV(t + 1, (t + 1) & 1);
        if (t + 1 < ntiles) { CP_WAIT1(); } else { CP_WAIT0(); }
        __syncthreads();

        const uint32_t stb = sb + AST_BASE + (uint32_t)(t & 1) * AST_B;

        // ---- scores S = Q K^T ----
        float c[8][4];
#pragma unroll
        for (int nt = 0; nt < 8; nt++)
#pragma unroll
            for (int e = 0; e < 4; e++) c[nt][e] = 0.f;

        if (!uniform) {
#pragma unroll
            for (int ks = 0; ks < 4; ks++) {
                const uint32_t kb = (uint32_t)(ks * 16 * 2);
#pragma unroll
                for (int g = 0; g < 4; g++) {
                    const uint32_t boff = (uint32_t)(((g * 16 + kRow) * APAD + kKof) * 2) + kb;
                    uint32_t kh4[4];
                    ldsm4(kh4[0], kh4[1], kh4[2], kh4[3], stb + AKH + boff);
                    mma_f16(c[2 * g],     qfh[ks], kh4 + 0);
                    mma_f16(c[2 * g],     qfl[ks], kh4 + 0);
                    mma_f16(c[2 * g + 1], qfh[ks], kh4 + 2);
                    mma_f16(c[2 * g + 1], qfl[ks], kh4 + 2);
                }
            }
        }

        // ---- scale + mask ----
        const int tilebase = t * ATK;
        const bool partial = (tilebase + ATK) > Leff;
#pragma unroll
        for (int nt = 0; nt < 8; nt++) {
#pragma unroll
            for (int e = 0; e < 4; e++) {
                float s = c[nt][e] * 0.125f;
                if (partial) {
                    int key = tilebase + nt * 8 + qrl * 2 + (e & 1);
                    if (key >= Leff) s = -FLT_MAX;
                }
                c[nt][e] = s;
            }
        }

        // ---- online softmax ----
        float rm0 = -FLT_MAX, rm1 = -FLT_MAX;
#pragma unroll
        for (int nt = 0; nt < 8; nt++) {
            rm0 = fmaxf(rm0, fmaxf(c[nt][0], c[nt][1]));
            rm1 = fmaxf(rm1, fmaxf(c[nt][2], c[nt][3]));
        }
#pragma unroll
        for (int off = 1; off <= 2; off <<= 1) {
            rm0 = fmaxf(rm0, __shfl_xor_sync(0xffffffffu, rm0, off));
            rm1 = fmaxf(rm1, __shfl_xor_sync(0xffffffffu, rm1, off));
        }
        const float mn0 = fmaxf(m0, rm0);
        const float mn1 = fmaxf(m1, rm1);
        const float al0 = __expf(m0 - mn0);
        const float al1 = __expf(m1 - mn1);
        m0 = mn0; m1 = mn1;

        float ps0 = 0.f, ps1 = 0.f;
        uint32_t ph01[8], ph23[8], pl01[8], pl23[8];
#pragma unroll
        for (int nt = 0; nt < 8; nt++) {
            float p0 = __expf(c[nt][0] - mn0);
            float p1 = __expf(c[nt][1] - mn0);
            float p2 = __expf(c[nt][2] - mn1);
            float p3 = __expf(c[nt][3] - mn1);
            ps0 += p0 + p1; ps1 += p2 + p3;
            float h0 = __half2float(__float2half_rn(p0));
            float h1 = __half2float(__float2half_rn(p1));
            float h2 = __half2float(__float2half_rn(p2));
            float h3 = __half2float(__float2half_rn(p3));
            ph01[nt] = pack_f16(h0, h1);
            ph23[nt] = pack_f16(h2, h3);
            pl01[nt] = pack_f16(p0 - h0, p1 - h1);
            pl23[nt] = pack_f16(p2 - h2, p3 - h3);
        }
#pragma unroll
        for (int off = 1; off <= 2; off <<= 1) {
            ps0 += __shfl_xor_sync(0xffffffffu, ps0, off);
            ps1 += __shfl_xor_sync(0xffffffffu, ps1, off);
        }
        l0 = l0 * al0 + ps0;
        l1 = l1 * al1 + ps1;
#pragma unroll
        for (int nt = 0; nt < 8; nt++) {
            O[nt][0] *= al0; O[nt][1] *= al0;
            O[nt][2] *= al1; O[nt][3] *= al1;
        }

        // ---- O += P V ----
#pragma unroll
        for (int tk = 0; tk < 4; tk++) {
            uint32_t ah[4]  = {ph01[2 * tk], ph23[2 * tk], ph01[2 * tk + 1], ph23[2 * tk + 1]};
            uint32_t alr[4] = {pl01[2 * tk], pl23[2 * tk], pl01[2 * tk + 1], pl23[2 * tk + 1]};
#pragma unroll
            for (int g = 0; g < 4; g++) {
                const uint32_t voff = (uint32_t)(((tk * 16 + vRow) * APAD + g * 16 + vCol) * 2);
                uint32_t vh4[4];
                ldsm4t(vh4[0], vh4[1], vh4[2], vh4[3], stb + AVH + voff);
                mma_f16(O[2 * g],     ah,  vh4 + 0);
                mma_f16(O[2 * g],     alr, vh4 + 0);
                mma_f16(O[2 * g + 1], ah,  vh4 + 2);
                mma_f16(O[2 * g + 1], alr, vh4 + 2);
            }
        }
        __syncthreads();
    }

    // ---- epilogue: normalize, split fp16, store concat layout ----
    const float inv0 = 1.f / l0;
    const float inv1 = 1.f / l1;
    const int q0g = qbase + w * 16 + gid;
    const int q1g = q0g + 8;
#pragma unroll
    for (int nt = 0; nt < 8; nt++) {
        const int col = h * 64 + nt * 8 + qrl * 2;
        size_t o0 = ((size_t)(b * SS + q0g)) * DD + col;
        size_t o1 = ((size_t)(b * SS + q1g)) * DD + col;
        float v0 = O[nt][0] * inv0, v1 = O[nt][1] * inv0;
        float v2 = O[nt][2] * inv1, v3 = O[nt][3] * inv1;
        float h0 = __half2float(__float2half_rn(v0));
        float h1 = __half2float(__float2half_rn(v1));
        float h2 = __half2float(__float2half_rn(v2));
        float h3 = __half2float(__float2half_rn(v3));
        *(uint32_t*)(outh + o0) = pack_f16(h0, h1);
        *(uint32_t*)(outl + o0) = pack_f16(v0 - h0, v1 - h1);
        *(uint32_t*)(outh + o1) = pack_f16(h2, h3);
        *(uint32_t*)(outl + o1) = pack_f16(v2 - h2, v3 - h3);
    }
}

// ---------------------------------------------------------------------------
extern "C" void kernel_launch(void* const* d_in, const int* in_sizes, int n_in,
                              void* d_out, int out_size)
{
    const float* Q  = (const float*)d_in[0];
    const float* Km = (const float*)d_in[1];
    const float* V  = (const float*)d_in[2];
    const int*   vl = (const int*)d_in[3];
    const float* Wq = (const float*)d_in[4];
    const float* Wk = (const float*)d_in[5];
    const float* Wv = (const float*)d_in[6];
    const float* Wo = (const float*)d_in[7];
    float* out = (float*)d_out;

    __half *qh, *ql, *kh, *kl, *vh, *vvl;
    __half *pqh, *pql, *pk, *pv, *ch, *cl, *wt;
    cudaGetSymbolAddress((void**)&qh, g_qh);   cudaGetSymbolAddress((void**)&ql, g_ql);
    cudaGetSymbolAddress((void**)&kh, g_kh);   cudaGetSymbolAddress((void**)&kl, g_kl);
    cudaGetSymbolAddress((void**)&vh, g_vh);   cudaGetSymbolAddress((void**)&vvl, g_vl);
    cudaGetSymbolAddress((void**)&pqh, g_pqh); cudaGetSymbolAddress((void**)&pql, g_pql);
    cudaGetSymbolAddress((void**)&pk, g_pk);   cudaGetSymbolAddress((void**)&pv, g_pv);
    cudaGetSymbolAddress((void**)&ch, g_ch);   cudaGetSymbolAddress((void**)&cl, g_cl);
    cudaGetSymbolAddress((void**)&wt, g_wt);

    cudaFuncSetAttribute(gemm_tc, cudaFuncAttributeMaxDynamicSharedMemorySize, SMEM_GEMM);
    cudaFuncSetAttribute(attn_tc, cudaFuncAttributeMaxDynamicSharedMemorySize, SMEM_ATTN);

    const int nblkSplit = (int)(NEL / 4 / 256);          // 8192
    split_kernel<<<nblkSplit, 256>>>((const float4*)Q,  (ushort4*)qh, (ushort4*)ql);
    split_kernel<<<nblkSplit, 256>>>((const float4*)Km, (ushort4*)kh, (ushort4*)kl);
    split_kernel<<<nblkSplit, 256>>>((const float4*)V,  (ushort4*)vh, (ushort4*)vvl);

    dim3 gW(32, 32), bW(32, 8);
    const float* Ws[4] = {Wq, Wk, Wv, Wo};
    for (int i = 0; i < 4; i++)
        wsplit_kernel<<<gW, bW>>>(Ws[i], wt + (size_t)i * DD * DD);

    dim3 gG(DD / 128, MROWS / 128);                       // (8, 64)
    gemm_tc<<<gG, 256, SMEM_GEMM>>>(qh, ql, wt + 0 * (size_t)DD * DD, nullptr, pqh, pql, 2);
    gemm_tc<<<gG, 256, SMEM_GEMM>>>(kh, kl, wt + 1 * (size_t)DD * DD, nullptr, pk, nullptr, 3);
    gemm_tc<<<gG, 256, SMEM_GEMM>>>(vh, vvl, wt + 2 * (size_t)DD * DD, nullptr, pv, nullptr, 3);

    dim3 gAttn(SS / ATQ, BB * HH);                        // (16, 64)
    attn_tc<<<gAttn, 256, SMEM_ATTN>>>(vl, ch, cl);

    gemm_tc<<<gG, 256, SMEM_GEMM>>>(ch, cl, wt + 3 * (size_t)DD * DD, out, nullptr, nullptr, 0);
}

// round 8
// speedup vs baseline: 7.0091x; 1.0646x over previous
#include <cuda_runtime.h>
#include <cuda_fp16.h>
#include <math.h>
#include <float.h>
#include <stdint.h>

// Problem constants
#define BB   4
#define SS   2048
#define DD   1024
#define HH   16
#define DH   64
#define MROWS (BB*SS)      // 8192

// ---------------------------------------------------------------------------
// Scratch (allocation-free rule: __device__ globals)
// ---------------------------------------------------------------------------
#define NEL ((size_t)MROWS*DD)               // 8M elements
__device__ __align__(16) __half g_qh[NEL], g_ql[NEL];
__device__ __align__(16) __half g_kh[NEL], g_kl[NEL];
__device__ __align__(16) __half g_vh[NEL], g_vl[NEL];
__device__ __align__(16) __half g_pqh[NEL], g_pql[NEL];
__device__ __align__(16) __half g_pk[NEL];
__device__ __align__(16) __half g_pv[NEL];
__device__ __align__(16) __half g_ch[NEL], g_cl[NEL];
__device__ __align__(16) __half g_wt[4][DD*DD];

// ---------------------------------------------------------------------------
// helpers
// ---------------------------------------------------------------------------
__device__ __forceinline__ uint32_t smem_u32(const void* p) {
    uint32_t a;
    asm("{ .reg .u64 t; cvta.to.shared.u64 t, %1; cvt.u32.u64 %0, t; }" : "=r"(a) : "l"(p));
    return a;
}
__device__ __forceinline__ void cp16(uint32_t dst, const void* src) {
    asm volatile("cp.async.cg.shared.global [%0], [%1], 16;" :: "r"(dst), "l"(src));
}
#define CP_COMMIT() asm volatile("cp.async.commit_group;" ::: "memory")
#define CP_WAIT2()  asm volatile("cp.async.wait_group 2;" ::: "memory")
#define CP_WAIT1()  asm volatile("cp.async.wait_group 1;" ::: "memory")
#define CP_WAIT0()  asm volatile("cp.async.wait_group 0;" ::: "memory")

__device__ __forceinline__ void ldsm4(uint32_t& r0, uint32_t& r1, uint32_t& r2, uint32_t& r3,
                                      uint32_t addr) {
    asm volatile("ldmatrix.sync.aligned.m8n8.x4.shared.b16 {%0,%1,%2,%3}, [%4];"
                 : "=r"(r0), "=r"(r1), "=r"(r2), "=r"(r3) : "r"(addr));
}
__device__ __forceinline__ void ldsm4t(uint32_t& r0, uint32_t& r1, uint32_t& r2, uint32_t& r3,
                                       uint32_t addr) {
    asm volatile("ldmatrix.sync.aligned.m8n8.x4.trans.shared.b16 {%0,%1,%2,%3}, [%4];"
                 : "=r"(r0), "=r"(r1), "=r"(r2), "=r"(r3) : "r"(addr));
}
__device__ __forceinline__ void mma_f16(float* c, const uint32_t* a, const uint32_t* b) {
    asm volatile(
        "mma.sync.aligned.m16n8k16.row.col.f32.f16.f16.f32 "
        "{%0,%1,%2,%3}, {%4,%5,%6,%7}, {%8,%9}, {%0,%1,%2,%3};"
        : "+f"(c[0]), "+f"(c[1]), "+f"(c[2]), "+f"(c[3])
        : "r"(a[0]), "r"(a[1]), "r"(a[2]), "r"(a[3]), "r"(b[0]), "r"(b[1]));
}
__device__ __forceinline__ uint32_t pack_f16(float lo, float hi) {
    __half2 t;
    t.x = __float2half_rn(lo);
    t.y = __float2half_rn(hi);
    return *reinterpret_cast<uint32_t*>(&t);
}

// ---------------------------------------------------------------------------
// valid_lens may physically be int32 (jax x64 disabled) or int64.
// ---------------------------------------------------------------------------
__device__ __forceinline__ int load_valid_len(const int* p, int b) {
    bool is64 = (p[1] == 0) && (p[3] == 0);
    int v = is64 ? p[2 * b] : p[b];
    if (v < 0) v = 0;
    if (v > SS) v = SS;
    return v;
}

// ---------------------------------------------------------------------------
// Fused elementwise fp32 -> (hi, lo) fp16 split for Q, K, V. z selects tensor.
// ---------------------------------------------------------------------------
__global__ __launch_bounds__(256) void split3_kernel(
    const float4* __restrict__ inQ, const float4* __restrict__ inK,
    const float4* __restrict__ inV)
{
    const int z = blockIdx.z;
    const float4* in = (z == 0) ? inQ : (z == 1) ? inK : inV;
    ushort4* hi = (ushort4*)((z == 0) ? g_qh : (z == 1) ? g_kh : g_vh);
    ushort4* lo = (ushort4*)((z == 0) ? g_ql : (z == 1) ? g_kl : g_vl);
    int i = blockIdx.x * 256 + threadIdx.x;
    float4 v = in[i];
    float f[4] = {v.x, v.y, v.z, v.w};
    unsigned short h[4], l[4];
#pragma unroll
    for (int j = 0; j < 4; j++) {
        __half hb = __float2half_rn(f[j]);
        __half lb = __float2half_rn(f[j] - __half2float(hb));
        h[j] = __half_as_ushort(hb);
        l[j] = __half_as_ushort(lb);
    }
    hi[i] = make_ushort4(h[0], h[1], h[2], h[3]);
    lo[i] = make_ushort4(l[0], l[1], l[2], l[3]);
}

// ---------------------------------------------------------------------------
// Fused W[k,n] -> wt[n,k] fp16 transpose for all 4 weights (z selects).
// ---------------------------------------------------------------------------
__global__ __launch_bounds__(256) void wsplit_kernel(
    const float* __restrict__ W0, const float* __restrict__ W1,
    const float* __restrict__ W2, const float* __restrict__ W3)
{
    __shared__ float tile[32][33];
    const int z = blockIdx.z;
    const float* W = (z == 0) ? W0 : (z == 1) ? W1 : (z == 2) ? W2 : W3;
    __half* th = g_wt[z];
    const int tx = threadIdx.x, ty = threadIdx.y;      // (32, 8)
    const int bk = blockIdx.x * 32, bn = blockIdx.y * 32;
#pragma unroll
    for (int i = 0; i < 4; i++)
        tile[ty + 8 * i][tx] = W[(size_t)(bk + ty + 8 * i) * DD + bn + tx];
    __syncthreads();
#pragma unroll
    for (int i = 0; i < 4; i++) {
        float f = tile[tx][ty + 8 * i];
        th[(size_t)(bn + ty + 8 * i) * DD + bk + tx] = __float2half_rn(f);
    }
}

// ---------------------------------------------------------------------------
// Tensor-core GEMM core (mma.sync fp16, 2-term split: Ah*Bh + Al*Bh).
// 3-stage cp.async pipeline, one __syncthreads per K-chunk.
// mode 0: C fp32 row-major. mode 2: fp16 hi/lo head-major. mode 3: fp16 single.
// ---------------------------------------------------------------------------
#define PADK    72
#define TILE_B  (128*PADK*2)        // 18432
#define OFF_AH  0
#define OFF_AL  (1*TILE_B)
#define OFF_BH  (2*TILE_B)
#define STAGE_B (3*TILE_B)          // 55296
#define SMEM_GEMM (3*STAGE_B)       // 165888

__device__ __forceinline__ void gemm_core(
    uint32_t sb,
    const uint4* __restrict__ pAh, const uint4* __restrict__ pAl,
    const uint4* __restrict__ pBh,
    float* __restrict__ C, __half* __restrict__ Chi, __half* __restrict__ Clo,
    int mode, int bm, int bn)
{
    const int tid  = threadIdx.x;
    const int wid  = tid >> 5;
    const int lane = tid & 31;

    const int lrow = tid >> 3;
    const int lc8  = tid & 7;

    float acc[4][4][4];
#pragma unroll
    for (int mt = 0; mt < 4; mt++)
#pragma unroll
        for (int nt = 0; nt < 4; nt++)
#pragma unroll
            for (int e = 0; e < 4; e++) acc[mt][nt][e] = 0.f;

    const int mbase = (wid & 1) * 64;
    const int nbase = (wid >> 1) * 32;
    const int aRow  = mbase + (lane & 15);
    const int aKoff = (lane >> 4) * 8;
    const int bRow  = nbase + (lane & 7) + ((lane >> 4) & 1) * 8;
    const int bKoff = ((lane >> 3) & 1) * 8;
    const uint32_t aOffBase = (uint32_t)((aRow * PADK + aKoff) * 2);
    const uint32_t bOffBase = (uint32_t)((bRow * PADK + bKoff) * 2);

    auto issue = [&](int c, int st) {
        const uint32_t stb = sb + (uint32_t)st * STAGE_B;
#pragma unroll
        for (int i = 0; i < 4; i++) {
            int row = lrow + i * 32;
            uint32_t so = stb + (uint32_t)((row * PADK + lc8 * 8) * 2);
            size_t ai = (size_t)(bm + row) * 128 + c * 8 + lc8;
            size_t bi = (size_t)(bn + row) * 128 + c * 8 + lc8;
            cp16(so + OFF_AH, pAh + ai);
            cp16(so + OFF_AL, pAl + ai);
            cp16(so + OFF_BH, pBh + bi);
        }
        CP_COMMIT();
    };

    issue(0, 0);
    issue(1, 1);

    for (int c = 0; c < 16; c++) {
        if (c < 15) { CP_WAIT1(); } else { CP_WAIT0(); }
        __syncthreads();
        if (c + 2 < 16) issue(c + 2, (c + 2) % 3);

        const uint32_t stb = sb + (uint32_t)(c % 3) * STAGE_B;
#pragma unroll
        for (int ks = 0; ks < 4; ks++) {
            const uint32_t kb = (uint32_t)(ks * 16 * 2);
            uint32_t bh[8];
            ldsm4(bh[0], bh[1], bh[2], bh[3], stb + OFF_BH + bOffBase + kb);
            ldsm4(bh[4], bh[5], bh[6], bh[7], stb + OFF_BH + bOffBase + kb + 16 * PADK * 2);
#pragma unroll
            for (int mt = 0; mt < 4; mt++) {
                const uint32_t aoff = aOffBase + (uint32_t)(mt * 16 * PADK * 2) + kb;
                uint32_t ah[4], al[4];
                ldsm4(ah[0], ah[1], ah[2], ah[3], stb + OFF_AH + aoff);
                ldsm4(al[0], al[1], al[2], al[3], stb + OFF_AL + aoff);
#pragma unroll
                for (int nt = 0; nt < 4; nt++) {
                    const uint32_t* bfh = &bh[(nt & 1) ? ((nt >> 1) * 4 + 2) : ((nt >> 1) * 4)];
                    mma_f16(acc[mt][nt], ah, bfh);
                    mma_f16(acc[mt][nt], al, bfh);
                }
            }
        }
    }

    const int rl = lane >> 2;
    const int cl = (lane & 3) * 2;
#pragma unroll
    for (int mt = 0; mt < 4; mt++) {
#pragma unroll
        for (int nt = 0; nt < 4; nt++) {
            const int row0 = bm + mbase + mt * 16 + rl;
            const int row1 = row0 + 8;
            const int colg = bn + nbase + nt * 8 + cl;
            float v0 = acc[mt][nt][0], v1 = acc[mt][nt][1];
            float v2 = acc[mt][nt][2], v3 = acc[mt][nt][3];
            if (mode == 0) {
                *(float2*)(C + (size_t)row0 * DD + colg) = make_float2(v0, v1);
                *(float2*)(C + (size_t)row1 * DD + colg) = make_float2(v2, v3);
            } else {
                const int h = colg >> 6, dh0 = colg & 63;
                const int b0 = row0 >> 11, s0 = row0 & 2047;
                const int b1 = row1 >> 11, s1 = row1 & 2047;
                size_t o0 = (((size_t)(b0 * HH + h)) * SS + s0) * DH + dh0;
                size_t o1 = (((size_t)(b1 * HH + h)) * SS + s1) * DH + dh0;
                if (mode == 3) {
                    *(uint32_t*)(Chi + o0) = pack_f16(v0, v1);
                    *(uint32_t*)(Chi + o1) = pack_f16(v2, v3);
                } else {
                    float h0 = __half2float(__float2half_rn(v0));
                    float h1 = __half2float(__float2half_rn(v1));
                    float h2 = __half2float(__float2half_rn(v2));
                    float h3 = __half2float(__float2half_rn(v3));
                    *(uint32_t*)(Chi + o0) = pack_f16(h0, h1);
                    *(uint32_t*)(Clo + o0) = pack_f16(v0 - h0, v1 - h1);
                    *(uint32_t*)(Chi + o1) = pack_f16(h2, h3);
                    *(uint32_t*)(Clo + o1) = pack_f16(v2 - h2, v3 - h3);
                }
            }
        }
    }
}

// Fused projection GEMM: z = 0 (Q, split out), 1 (K), 2 (V).
__global__ __launch_bounds__(256) void gemm_proj(void)
{
    extern __shared__ char smem[];
    const uint32_t sb = smem_u32(smem);
    const int z = blockIdx.z;
    const uint4* pAh = (const uint4*)((z == 0) ? g_qh : (z == 1) ? g_kh : g_vh);
    const uint4* pAl = (const uint4*)((z == 0) ? g_ql : (z == 1) ? g_kl : g_vl);
    const uint4* pBh = (const uint4*)g_wt[z];
    __half* Chi = (z == 0) ? g_pqh : (z == 1) ? g_pk : g_pv;
    __half* Clo = (z == 0) ? g_pql : nullptr;
    const int mode = (z == 0) ? 2 : 3;
    gemm_core(sb, pAh, pAl, pBh, nullptr, Chi, Clo, mode,
              blockIdx.y * 128, blockIdx.x * 128);
}

// Output projection GEMM.
__global__ __launch_bounds__(256) void gemm_out(float* __restrict__ C)
{
    extern __shared__ char smem[];
    const uint32_t sb = smem_u32(smem);
    gemm_core(sb, (const uint4*)g_ch, (const uint4*)g_cl, (const uint4*)g_wt[3],
              C, nullptr, nullptr, 0, blockIdx.y * 128, blockIdx.x * 128);
}

// ---------------------------------------------------------------------------
// Flash attention with mma.sync fp16 (2-term QK and PV), 3-stage pipeline.
// ---------------------------------------------------------------------------
#define ATQ  128
#define ATK  64
#define APAD 72
#define AT_TILE (ATK*APAD*2)          // 9216
#define AQ_OFF_H 0
#define AQ_OFF_L (ATQ*APAD*2)         // 18432
#define AST_BASE (2*ATQ*APAD*2)       // 36864
#define AST_B    (2*AT_TILE)          // 18432 per stage (K, V)
#define AKH 0
#define AVH (1*AT_TILE)
#define SMEM_ATTN (AST_BASE + 3*AST_B)   // 92160

__global__ __launch_bounds__(256) void attn_tc(
    const int* __restrict__ valid_lens_raw,
    __half* __restrict__ outh, __half* __restrict__ outl)
{
    extern __shared__ char smem[];
    const uint32_t sb = smem_u32(smem);
    const int tid  = threadIdx.x;
    const int w    = tid >> 5;
    const int lane = tid & 31;
    const int bh   = blockIdx.y;
    const int b    = bh >> 4;
    const int h    = bh & 15;
    const int qbase = blockIdx.x * ATQ;

    const int L = load_valid_len(valid_lens_raw, b);
    const bool uniform = (L == 0);
    const int Leff = uniform ? SS : L;
    const int ntiles = (Leff + ATK - 1) >> 6;

    const uint4* pQh = (const uint4*)g_pqh;
    const uint4* pQl = (const uint4*)g_pql;
    const uint4* pK  = (const uint4*)g_pk;
    const uint4* pV  = (const uint4*)g_pv;

    // ---- issue Q load (one group) ----
    {
#pragma unroll
        for (int i = 0; i < 4; i++) {
            int g = tid + i * 256;
            int row = g >> 3, c8 = g & 7;
            size_t gi = ((size_t)bh * SS + qbase + row) * 8 + c8;
            uint32_t so = (uint32_t)((row * APAD + c8 * 8) * 2);
            cp16(sb + AQ_OFF_H + so, pQh + gi);
            cp16(sb + AQ_OFF_L + so, pQl + gi);
        }
        CP_COMMIT();
    }

    auto issueKV = [&](int t, int st) {
        const uint32_t stb = sb + AST_BASE + (uint32_t)st * AST_B;
        const int kb = t * ATK;
#pragma unroll
        for (int i = 0; i < 2; i++) {
            int g = tid + i * 256;
            int row = g >> 3, c8 = g & 7;
            size_t gi = ((size_t)bh * SS + kb + row) * 8 + c8;
            uint32_t so = (uint32_t)((row * APAD + c8 * 8) * 2);
            cp16(stb + AKH + so, pK + gi);
            cp16(stb + AVH + so, pV + gi);
        }
        CP_COMMIT();
    };

    issueKV(0, 0);
    if (ntiles > 1) { issueKV(1, 1); CP_WAIT2(); } else { CP_WAIT1(); }
    __syncthreads();

    // ---- Q fragments into registers ----
    const int gid = lane >> 2;
    const int qrl = lane & 3;
    uint32_t qfh[4][4], qfl[4][4];
    {
        const int aRow = w * 16 + (lane & 15);
        const uint32_t aoff0 = (uint32_t)((aRow * APAD + (lane >> 4) * 8) * 2);
#pragma unroll
        for (int ks = 0; ks < 4; ks++) {
            uint32_t kb = (uint32_t)(ks * 16 * 2);
            ldsm4(qfh[ks][0], qfh[ks][1], qfh[ks][2], qfh[ks][3], sb + AQ_OFF_H + aoff0 + kb);
            ldsm4(qfl[ks][0], qfl[ks][1], qfl[ks][2], qfl[ks][3], sb + AQ_OFF_L + aoff0 + kb);
        }
    }

    float O[8][4];
#pragma unroll
    for (int nt = 0; nt < 8; nt++)
#pragma unroll
        for (int e = 0; e < 4; e++) O[nt][e] = 0.f;
    float m0 = -FLT_MAX, m1 = -FLT_MAX, l0 = 0.f, l1 = 0.f;

    const int kRow = (lane & 7) + ((lane >> 4) & 1) * 8;
    const int kKof = ((lane >> 3) & 1) * 8;
    const int vRow = lane & 15;
    const int vCol = (lane >> 4) * 8;

    for (int t = 0; t < ntiles; t++) {
        if (t < ntiles - 1) { CP_WAIT1(); } else { CP_WAIT0(); }
        __syncthreads();
        if (t + 2 < ntiles) issueKV(t + 2, (t + 2) % 3);

        const uint32_t stb = sb + AST_BASE + (uint32_t)(t % 3) * AST_B;

        // ---- scores S = Q K^T ----
        float c[8][4];
#pragma unroll
        for (int nt = 0; nt < 8; nt++)
#pragma unroll
            for (int e = 0; e < 4; e++) c[nt][e] = 0.f;

        if (!uniform) {
#pragma unroll
            for (int ks = 0; ks < 4; ks++) {
                const uint32_t kb = (uint32_t)(ks * 16 * 2);
#pragma unroll
                for (int g = 0; g < 4; g++) {
                    const uint32_t boff = (uint32_t)(((g * 16 + kRow) * APAD + kKof) * 2) + kb;
                    uint32_t kh4[4];
                    ldsm4(kh4[0], kh4[1], kh4[2], kh4[3], stb + AKH + boff);
                    mma_f16(c[2 * g],     qfh[ks], kh4 + 0);
                    mma_f16(c[2 * g],     qfl[ks], kh4 + 0);
                    mma_f16(c[2 * g + 1], qfh[ks], kh4 + 2);
                    mma_f16(c[2 * g + 1], qfl[ks], kh4 + 2);
                }
            }
        }

        // ---- scale + mask ----
        const int tilebase = t * ATK;
        const bool partial = (tilebase + ATK) > Leff;
#pragma unroll
        for (int nt = 0; nt < 8; nt++) {
#pragma unroll
            for (int e = 0; e < 4; e++) {
                float s = c[nt][e] * 0.125f;
                if (partial) {
                    int key = tilebase + nt * 8 + qrl * 2 + (e & 1);
                    if (key >= Leff) s = -FLT_MAX;
                }
                c[nt][e] = s;
            }
        }

        // ---- online softmax ----
        float rm0 = -FLT_MAX, rm1 = -FLT_MAX;
#pragma unroll
        for (int nt = 0; nt < 8; nt++) {
            rm0 = fmaxf(rm0, fmaxf(c[nt][0], c[nt][1]));
            rm1 = fmaxf(rm1, fmaxf(c[nt][2], c[nt][3]));
        }
#pragma unroll
        for (int off = 1; off <= 2; off <<= 1) {
            rm0 = fmaxf(rm0, __shfl_xor_sync(0xffffffffu, rm0, off));
            rm1 = fmaxf(rm1, __shfl_xor_sync(0xffffffffu, rm1, off));
        }
        const float mn0 = fmaxf(m0, rm0);
        const float mn1 = fmaxf(m1, rm1);
        const float al0 = __expf(m0 - mn0);
        const float al1 = __expf(m1 - mn1);
        m0 = mn0; m1 = mn1;

        float ps0 = 0.f, ps1 = 0.f;
        uint32_t ph01[8], ph23[8], pl01[8], pl23[8];
#pragma unroll
        for (int nt = 0; nt < 8; nt++) {
            float p0 = __expf(c[nt][0] - mn0);
            float p1 = __expf(c[nt][1] - mn0);
            float p2 = __expf(c[nt][2] - mn1);
            float p3 = __expf(c[nt][3] - mn1);
            ps0 += p0 + p1; ps1 += p2 + p3;
            float h0 = __half2float(__float2half_rn(p0));
            float h1 = __half2float(__float2half_rn(p1));
            float h2 = __half2float(__float2half_rn(p2));
            float h3 = __half2float(__float2half_rn(p3));
            ph01[nt] = pack_f16(h0, h1);
            ph23[nt] = pack_f16(h2, h3);
            pl01[nt] = pack_f16(p0 - h0, p1 - h1);
            pl23[nt] = pack_f16(p2 - h2, p3 - h3);
        }
#pragma unroll
        for (int off = 1; off <= 2; off <<= 1) {
            ps0 += __shfl_xor_sync(0xffffffffu, ps0, off);
            ps1 += __shfl_xor_sync(0xffffffffu, ps1, off);
        }
        l0 = l0 * al0 + ps0;
        l1 = l1 * al1 + ps1;
#pragma unroll
        for (int nt = 0; nt < 8; nt++) {
            O[nt][0] *= al0; O[nt][1] *= al0;
            O[nt][2] *= al1; O[nt][3] *= al1;
        }

        // ---- O += P V ----
#pragma unroll
        for (int tk = 0; tk < 4; tk++) {
            uint32_t ah[4]  = {ph01[2 * tk], ph23[2 * tk], ph01[2 * tk + 1], ph23[2 * tk + 1]};
            uint32_t alr[4] = {pl01[2 * tk], pl23[2 * tk], pl01[2 * tk + 1], pl23[2 * tk + 1]};
#pragma unroll
            for (int g = 0; g < 4; g++) {
                const uint32_t voff = (uint32_t)(((tk * 16 + vRow) * APAD + g * 16 + vCol) * 2);
                uint32_t vh4[4];
                ldsm4t(vh4[0], vh4[1], vh4[2], vh4[3], stb + AVH + voff);
                mma_f16(O[2 * g],     ah,  vh4 + 0);
                mma_f16(O[2 * g],     alr, vh4 + 0);
                mma_f16(O[2 * g + 1], ah,  vh4 + 2);
                mma_f16(O[2 * g + 1], alr, vh4 + 2);
            }
        }
    }

    // ---- epilogue: normalize, split fp16, store concat layout ----
    const float inv0 = 1.f / l0;
    const float inv1 = 1.f / l1;
    const int q0g = qbase + w * 16 + gid;
    const int q1g = q0g + 8;
#pragma unroll
    for (int nt = 0; nt < 8; nt++) {
        const int col = h * 64 + nt * 8 + qrl * 2;
        size_t o0 = ((size_t)(b * SS + q0g)) * DD + col;
        size_t o1 = ((size_t)(b * SS + q1g)) * DD + col;
        float v0 = O[nt][0] * inv0, v1 = O[nt][1] * inv0;
        float v2 = O[nt][2] * inv1, v3 = O[nt][3] * inv1;
        float h0 = __half2float(__float2half_rn(v0));
        float h1 = __half2float(__float2half_rn(v1));
        float h2 = __half2float(__float2half_rn(v2));
        float h3 = __half2float(__float2half_rn(v3));
        *(uint32_t*)(outh + o0) = pack_f16(h0, h1);
        *(uint32_t*)(outl + o0) = pack_f16(v0 - h0, v1 - h1);
        *(uint32_t*)(outh + o1) = pack_f16(h2, h3);
        *(uint32_t*)(outl + o1) = pack_f16(v2 - h2, v3 - h3);
    }
}

// ---------------------------------------------------------------------------
extern "C" void kernel_launch(void* const* d_in, const int* in_sizes, int n_in,
                              void* d_out, int out_size)
{
    const float* Q  = (const float*)d_in[0];
    const float* Km = (const float*)d_in[1];
    const float* V  = (const float*)d_in[2];
    const int*   vl = (const int*)d_in[3];
    const float* Wq = (const float*)d_in[4];
    const float* Wk = (const float*)d_in[5];
    const float* Wv = (const float*)d_in[6];
    const float* Wo = (const float*)d_in[7];
    float* out = (float*)d_out;

    __half *ch, *cl;
    cudaGetSymbolAddress((void**)&ch, g_ch);
    cudaGetSymbolAddress((void**)&cl, g_cl);

    cudaFuncSetAttribute(gemm_proj, cudaFuncAttributeMaxDynamicSharedMemorySize, SMEM_GEMM);
    cudaFuncSetAttribute(gemm_out,  cudaFuncAttributeMaxDynamicSharedMemorySize, SMEM_GEMM);
    cudaFuncSetAttribute(attn_tc,   cudaFuncAttributeMaxDynamicSharedMemorySize, SMEM_ATTN);

    dim3 gSplit((unsigned)(NEL / 4 / 256), 1, 3);
    split3_kernel<<<gSplit, 256>>>((const float4*)Q, (const float4*)Km, (const float4*)V);

    dim3 gW(32, 32, 4), bW(32, 8);
    wsplit_kernel<<<gW, bW>>>(Wq, Wk, Wv, Wo);

    dim3 gProj(DD / 128, MROWS / 128, 3);                 // (8, 64, 3)
    gemm_proj<<<gProj, 256, SMEM_GEMM>>>();

    dim3 gAttn(SS / ATQ, BB * HH);                        // (16, 64)
    attn_tc<<<gAttn, 256, SMEM_ATTN>>>(vl, ch, cl);

    dim3 gOut(DD / 128, MROWS / 128);                     // (8, 64)
    gemm_out<<<gOut, 256, SMEM_GEMM>>>(out);
}